// round 3
// baseline (speedup 1.0000x reference)
#include <cuda_runtime.h>
#include <math.h>

#define BATCH 4
#define TLEN 2048
#define DMODEL 1024
#define NH 16
#define HP 64
#define FFDIM 4096
#define NTOK (BATCH * TLEN)   // 8192

// ---------------- scratch (static __device__, allocation-free) ----------------
__device__ float g_nX   [(size_t)NTOK * DMODEL];
__device__ float g_Q    [(size_t)NTOK * DMODEL];
__device__ float g_Kt   [(size_t)NTOK * DMODEL];
__device__ float g_V    [(size_t)NTOK * DMODEL];
__device__ float g_nv   [(size_t)NTOK * DMODEL];
__device__ float g_ss   [(size_t)NTOK * DMODEL];
__device__ float g_preff[(size_t)NTOK * DMODEL];
__device__ float g_hidden[(size_t)NTOK * FFDIM];
__device__ float g_Wq[DMODEL * DMODEL];
__device__ float g_Wk[DMODEL * DMODEL];
__device__ float g_Wv[DMODEL * DMODEL];

// ---------------- LayerNorm (one block per row of 1024) ----------------
// out = LN(x)*g + b (+ resid if non-null)
__global__ void __launch_bounds__(256) ln_kernel(
    const float* __restrict__ x, const float* __restrict__ g,
    const float* __restrict__ b, const float* __restrict__ resid,
    float* __restrict__ out)
{
    int row = blockIdx.x;
    int t = threadIdx.x;
    const float4* xr = (const float4*)(x + (size_t)row * DMODEL);
    float4 v = xr[t];
    float s  = v.x + v.y + v.z + v.w;
    float s2 = v.x*v.x + v.y*v.y + v.z*v.z + v.w*v.w;
    #pragma unroll
    for (int o = 16; o > 0; o >>= 1) {
        s  += __shfl_xor_sync(0xffffffffu, s,  o);
        s2 += __shfl_xor_sync(0xffffffffu, s2, o);
    }
    __shared__ float shs[8], shs2[8];
    __shared__ float mean_s, rstd_s;
    int wid = t >> 5, lane = t & 31;
    if (lane == 0) { shs[wid] = s; shs2[wid] = s2; }
    __syncthreads();
    if (t == 0) {
        float ts = 0.f, ts2 = 0.f;
        #pragma unroll
        for (int i = 0; i < 8; i++) { ts += shs[i]; ts2 += shs2[i]; }
        float mean = ts * (1.0f / DMODEL);
        float var  = ts2 * (1.0f / DMODEL) - mean * mean;
        mean_s = mean;
        rstd_s = rsqrtf(var + 1e-5f);
    }
    __syncthreads();
    float m = mean_s, r = rstd_s;
    float4 gv = ((const float4*)g)[t];
    float4 bv = ((const float4*)b)[t];
    float4 o;
    o.x = (v.x - m) * r * gv.x + bv.x;
    o.y = (v.y - m) * r * gv.y + bv.y;
    o.z = (v.z - m) * r * gv.z + bv.z;
    o.w = (v.w - m) * r * gv.w + bv.w;
    if (resid) {
        float4 rv = ((const float4*)(resid + (size_t)row * DMODEL))[t];
        o.x += rv.x; o.y += rv.y; o.z += rv.z; o.w += rv.w;
    }
    ((float4*)(out + (size_t)row * DMODEL))[t] = o;
}

// ---------------- weight transpose: (h,d,p) -> (d, h*P+p) ----------------
__global__ void transpose_w(const float* __restrict__ in, float* __restrict__ out)
{
    int idx = blockIdx.x * blockDim.x + threadIdx.x;
    if (idx >= DMODEL * DMODEL) return;
    int p = idx & (HP - 1);
    int d = (idx >> 6) & (DMODEL - 1);
    int h = idx >> 16;
    out[d * DMODEL + h * HP + p] = in[idx];
}

// ---------------- generic row-major GEMM: C = A[M,K] @ B[K,N] ----------------
// BM=BN=128, BK=16, 256 threads, 8x8 per thread. Dims must be /128 and /16.
template<bool BIAS, bool GELU, bool RESID>
__global__ void __launch_bounds__(256) gemm_nn(
    const float* __restrict__ A, const float* __restrict__ B,
    const float* __restrict__ bias, const float* __restrict__ resid,
    float* __restrict__ C, int M, int N, int K)
{
    __shared__ float As[16][128];
    __shared__ float Bs[16][128];
    int t = threadIdx.x;
    int row0 = blockIdx.y * 128, col0 = blockIdx.x * 128;
    int ty = t >> 4, tx = t & 15;
    float acc[8][8];
    #pragma unroll
    for (int i = 0; i < 8; i++)
        #pragma unroll
        for (int j = 0; j < 8; j++) acc[i][j] = 0.f;

    const float* Aptr = A + (size_t)row0 * K;
    const float* Bptr = B + col0;

    for (int k0 = 0; k0 < K; k0 += 16) {
        #pragma unroll
        for (int i = 0; i < 2; i++) {
            int f = t + i * 256;
            int r = f >> 2, c4 = f & 3;
            float4 av = *(const float4*)(Aptr + (size_t)r * K + k0 + c4 * 4);
            As[c4*4+0][r] = av.x; As[c4*4+1][r] = av.y;
            As[c4*4+2][r] = av.z; As[c4*4+3][r] = av.w;
        }
        #pragma unroll
        for (int i = 0; i < 2; i++) {
            int f = t + i * 256;
            int r = f >> 5, c4 = f & 31;
            *(float4*)&Bs[r][c4*4] = *(const float4*)(Bptr + (size_t)(k0 + r) * N + c4 * 4);
        }
        __syncthreads();
        #pragma unroll
        for (int k = 0; k < 16; k++) {
            float a[8], bb[8];
            #pragma unroll
            for (int i = 0; i < 8; i++) a[i]  = As[k][ty*8 + i];
            #pragma unroll
            for (int j = 0; j < 8; j++) bb[j] = Bs[k][tx*8 + j];
            #pragma unroll
            for (int i = 0; i < 8; i++)
                #pragma unroll
                for (int j = 0; j < 8; j++) acc[i][j] = fmaf(a[i], bb[j], acc[i][j]);
        }
        __syncthreads();
    }

    #pragma unroll
    for (int i = 0; i < 8; i++) {
        int r = row0 + ty * 8 + i;
        #pragma unroll
        for (int j = 0; j < 8; j++) {
            int c = col0 + tx * 8 + j;
            float v = acc[i][j];
            if (BIAS)  v += bias[c];
            if (GELU)  v = 0.5f * v * (1.0f + erff(v * 0.70710678118654752f));
            if (RESID) v += resid[(size_t)r * N + c];
            C[(size_t)r * N + c] = v;
        }
    }
}

// ---------------- attention scores: S[q,k] = (K_q . Q_k) / 8 ----------------
// per (b,h): A = K-view [T,64] ld=1024, B = Q-view [T,64] ld=1024 (B^T GEMM)
__global__ void __launch_bounds__(256) score_gemm(
    const float* __restrict__ Kmat, const float* __restrict__ Qmat,
    float* __restrict__ S)
{
    __shared__ float Ks[16][128];
    __shared__ float Qs[16][128];
    int t = threadIdx.x;
    int bh = blockIdx.z;
    int b = bh >> 4, h = bh & 15;
    const float* Kb = Kmat + (size_t)b * TLEN * DMODEL + h * HP + (size_t)(blockIdx.y * 128) * DMODEL;
    const float* Qb = Qmat + (size_t)b * TLEN * DMODEL + h * HP + (size_t)(blockIdx.x * 128) * DMODEL;
    float* Sb = S + (size_t)bh * TLEN * TLEN;
    int ty = t >> 4, tx = t & 15;
    float acc[8][8];
    #pragma unroll
    for (int i = 0; i < 8; i++)
        #pragma unroll
        for (int j = 0; j < 8; j++) acc[i][j] = 0.f;

    for (int p0 = 0; p0 < HP; p0 += 16) {
        #pragma unroll
        for (int i = 0; i < 2; i++) {
            int f = t + i * 256;
            int r = f >> 2, c4 = f & 3;
            float4 kv = *(const float4*)(Kb + (size_t)r * DMODEL + p0 + c4 * 4);
            Ks[c4*4+0][r] = kv.x; Ks[c4*4+1][r] = kv.y;
            Ks[c4*4+2][r] = kv.z; Ks[c4*4+3][r] = kv.w;
            float4 qv = *(const float4*)(Qb + (size_t)r * DMODEL + p0 + c4 * 4);
            Qs[c4*4+0][r] = qv.x; Qs[c4*4+1][r] = qv.y;
            Qs[c4*4+2][r] = qv.z; Qs[c4*4+3][r] = qv.w;
        }
        __syncthreads();
        #pragma unroll
        for (int k = 0; k < 16; k++) {
            float a[8], bb[8];
            #pragma unroll
            for (int i = 0; i < 8; i++) a[i]  = Ks[k][ty*8 + i];
            #pragma unroll
            for (int j = 0; j < 8; j++) bb[j] = Qs[k][tx*8 + j];
            #pragma unroll
            for (int i = 0; i < 8; i++)
                #pragma unroll
                for (int j = 0; j < 8; j++) acc[i][j] = fmaf(a[i], bb[j], acc[i][j]);
        }
        __syncthreads();
    }
    #pragma unroll
    for (int i = 0; i < 8; i++) {
        int q = blockIdx.y * 128 + ty * 8 + i;
        #pragma unroll
        for (int j = 0; j < 8; j++) {
            int k = blockIdx.x * 128 + tx * 8 + j;
            Sb[(size_t)q * TLEN + k] = acc[i][j] * 0.125f;
        }
    }
}

// ---------------- row softmax over 2048 (in-place) ----------------
__global__ void __launch_bounds__(256) softmax_kernel(float* __restrict__ S)
{
    size_t row = blockIdx.x;
    float* r = S + row * (size_t)TLEN;
    int t = threadIdx.x;
    float4 v0 = ((float4*)r)[t];
    float4 v1 = ((float4*)r)[t + 256];
    float mx = fmaxf(fmaxf(fmaxf(v0.x, v0.y), fmaxf(v0.z, v0.w)),
                     fmaxf(fmaxf(v1.x, v1.y), fmaxf(v1.z, v1.w)));
    #pragma unroll
    for (int o = 16; o > 0; o >>= 1) mx = fmaxf(mx, __shfl_xor_sync(0xffffffffu, mx, o));
    __shared__ float sm[8];
    __shared__ float mx_s, inv_s;
    int wid = t >> 5, lane = t & 31;
    if (lane == 0) sm[wid] = mx;
    __syncthreads();
    if (t == 0) {
        float m = sm[0];
        #pragma unroll
        for (int i = 1; i < 8; i++) m = fmaxf(m, sm[i]);
        mx_s = m;
    }
    __syncthreads();
    float m = mx_s;
    v0.x = __expf(v0.x - m); v0.y = __expf(v0.y - m);
    v0.z = __expf(v0.z - m); v0.w = __expf(v0.w - m);
    v1.x = __expf(v1.x - m); v1.y = __expf(v1.y - m);
    v1.z = __expf(v1.z - m); v1.w = __expf(v1.w - m);
    float s = v0.x + v0.y + v0.z + v0.w + v1.x + v1.y + v1.z + v1.w;
    #pragma unroll
    for (int o = 16; o > 0; o >>= 1) s += __shfl_xor_sync(0xffffffffu, s, o);
    if (lane == 0) sm[wid] = s;
    __syncthreads();
    if (t == 0) {
        float ts = 0.f;
        #pragma unroll
        for (int i = 0; i < 8; i++) ts += sm[i];
        inv_s = 1.0f / ts;
    }
    __syncthreads();
    float inv = inv_s;
    v0.x *= inv; v0.y *= inv; v0.z *= inv; v0.w *= inv;
    v1.x *= inv; v1.y *= inv; v1.z *= inv; v1.w *= inv;
    ((float4*)r)[t] = v0;
    ((float4*)r)[t + 256] = v1;
}

// ---------------- AV: nv[q,:] = sum_k attn[q,k] * V[k,:]  (per b,h) ----------------
// BM=128, BN=64 (full head dim), BK=32, 256 threads, 8x4 per thread
__global__ void __launch_bounds__(256) av_gemm(
    const float* __restrict__ Attn, const float* __restrict__ V,
    float* __restrict__ O)
{
    __shared__ float As[32][128];
    __shared__ float Bs[32][64];
    int t = threadIdx.x;
    int bh = blockIdx.z;
    int b = bh >> 4, h = bh & 15;
    const float* Ab = Attn + (size_t)bh * TLEN * TLEN + (size_t)(blockIdx.x * 128) * TLEN;
    const float* Vb = V + (size_t)b * TLEN * DMODEL + h * HP;
    float* Ob = O + (size_t)b * TLEN * DMODEL + h * HP + (size_t)(blockIdx.x * 128) * DMODEL;
    int ty = t >> 4, tx = t & 15;
    float acc[8][4];
    #pragma unroll
    for (int i = 0; i < 8; i++)
        #pragma unroll
        for (int j = 0; j < 4; j++) acc[i][j] = 0.f;

    for (int k0 = 0; k0 < TLEN; k0 += 32) {
        #pragma unroll
        for (int i = 0; i < 4; i++) {
            int f = t + i * 256;
            int r = f >> 3, c4 = f & 7;
            float4 av = *(const float4*)(Ab + (size_t)r * TLEN + k0 + c4 * 4);
            As[c4*4+0][r] = av.x; As[c4*4+1][r] = av.y;
            As[c4*4+2][r] = av.z; As[c4*4+3][r] = av.w;
        }
        #pragma unroll
        for (int i = 0; i < 2; i++) {
            int f = t + i * 256;
            int r = f >> 4, c4 = f & 15;
            *(float4*)&Bs[r][c4*4] = *(const float4*)(Vb + (size_t)(k0 + r) * DMODEL + c4 * 4);
        }
        __syncthreads();
        #pragma unroll
        for (int k = 0; k < 32; k++) {
            float a[8], bb[4];
            #pragma unroll
            for (int i = 0; i < 8; i++) a[i]  = As[k][ty*8 + i];
            #pragma unroll
            for (int j = 0; j < 4; j++) bb[j] = Bs[k][tx*4 + j];
            #pragma unroll
            for (int i = 0; i < 8; i++)
                #pragma unroll
                for (int j = 0; j < 4; j++) acc[i][j] = fmaf(a[i], bb[j], acc[i][j]);
        }
        __syncthreads();
    }
    #pragma unroll
    for (int i = 0; i < 8; i++)
        #pragma unroll
        for (int j = 0; j < 4; j++)
            Ob[(size_t)(ty*8 + i) * DMODEL + tx*4 + j] = acc[i][j];
}

// ---------------- launch ----------------
extern "C" void kernel_launch(void* const* d_in, const int* in_sizes, int n_in,
                              void* d_out, int out_size)
{
    const float* X      = (const float*)d_in[0];
    const float* WQ     = (const float*)d_in[1];
    const float* WK     = (const float*)d_in[2];
    const float* WV     = (const float*)d_in[3];
    const float* WO     = (const float*)d_in[4];
    const float* attn_g = (const float*)d_in[5];
    const float* attn_b = (const float*)d_in[6];
    const float* ff_g   = (const float*)d_in[7];
    const float* ff_b   = (const float*)d_in[8];
    const float* fW1    = (const float*)d_in[9];
    const float* fb1    = (const float*)d_in[10];
    const float* fW2    = (const float*)d_in[11];
    const float* fb2    = (const float*)d_in[12];

    float* out  = (float*)d_out;
    float* attn = out + (size_t)NTOK * DMODEL;   // [B,H,T,T]

    float *nX, *Q, *K, *V, *nv, *ss, *preff, *hidden, *Wq, *Wk, *Wv;
    cudaGetSymbolAddress((void**)&nX,     g_nX);
    cudaGetSymbolAddress((void**)&Q,      g_Q);
    cudaGetSymbolAddress((void**)&K,      g_Kt);
    cudaGetSymbolAddress((void**)&V,      g_V);
    cudaGetSymbolAddress((void**)&nv,     g_nv);
    cudaGetSymbolAddress((void**)&ss,     g_ss);
    cudaGetSymbolAddress((void**)&preff,  g_preff);
    cudaGetSymbolAddress((void**)&hidden, g_hidden);
    cudaGetSymbolAddress((void**)&Wq,     g_Wq);
    cudaGetSymbolAddress((void**)&Wk,     g_Wk);
    cudaGetSymbolAddress((void**)&Wv,     g_Wv);

    // 1. nX = LN(X)
    ln_kernel<<<NTOK, 256>>>(X, attn_g, attn_b, nullptr, nX);

    // 2. transpose weights: (h,d,p) -> (d, h*P+p)
    transpose_w<<<4096, 256>>>(WQ, Wq);
    transpose_w<<<4096, 256>>>(WK, Wk);
    transpose_w<<<4096, 256>>>(WV, Wv);

    // 3. Q/K/V projections
    dim3 gQKV(DMODEL / 128, NTOK / 128);
    gemm_nn<false, false, false><<<gQKV, 256>>>(nX, Wq, nullptr, nullptr, Q, NTOK, DMODEL, DMODEL);
    gemm_nn<false, false, false><<<gQKV, 256>>>(nX, Wk, nullptr, nullptr, K, NTOK, DMODEL, DMODEL);
    gemm_nn<false, false, false><<<gQKV, 256>>>(nX, Wv, nullptr, nullptr, V, NTOK, DMODEL, DMODEL);

    // 4. scores -> attn buffer; 5. softmax in-place; 6. nv = attn @ V
    score_gemm<<<dim3(TLEN / 128, TLEN / 128, BATCH * NH), 256>>>(K, Q, attn);
    softmax_kernel<<<BATCH * NH * TLEN, 256>>>(attn);
    av_gemm<<<dim3(TLEN / 128, 1, BATCH * NH), 256>>>(attn, V, nv);

    // 7. seq_summary = nv @ WO  (WO already [H*P, D] contiguous)
    gemm_nn<false, false, false><<<gQKV, 256>>>(nv, WO, nullptr, nullptr, ss, NTOK, DMODEL, DMODEL);

    // 8. pre_ff = X + LN(ss)
    ln_kernel<<<NTOK, 256>>>(ss, ff_g, ff_b, X, preff);

    // 9. hidden = gelu(pre_ff @ fW1 + fb1)
    gemm_nn<true, true, false><<<dim3(FFDIM / 128, NTOK / 128), 256>>>(
        preff, fW1, fb1, nullptr, hidden, NTOK, FFDIM, DMODEL);

    // 10. out = hidden @ fW2 + fb2 + pre_ff
    gemm_nn<true, false, true><<<dim3(DMODEL / 128, NTOK / 128), 256>>>(
        hidden, fW2, fb2, preff, out, NTOK, DMODEL, FFDIM);
}

// round 5
// speedup vs baseline: 1.0441x; 1.0441x over previous
#include <cuda_runtime.h>
#include <math.h>

#define BATCH 4
#define TLEN 2048
#define DMODEL 1024
#define NH 16
#define HP 64
#define FFDIM 4096
#define NTOK (BATCH * TLEN)   // 8192

// ---------------- scratch (static __device__, allocation-free) ----------------
__device__ float g_nX   [(size_t)NTOK * DMODEL];
__device__ float g_Q    [(size_t)NTOK * DMODEL];
__device__ float g_Kt   [(size_t)NTOK * DMODEL];
__device__ float g_V    [(size_t)NTOK * DMODEL];
__device__ float g_nv   [(size_t)NTOK * DMODEL];
__device__ float g_ss   [(size_t)NTOK * DMODEL];
__device__ float g_preff[(size_t)NTOK * DMODEL];
__device__ float g_hidden[(size_t)NTOK * FFDIM];
__device__ float g_Wq[DMODEL * DMODEL];
__device__ float g_Wk[DMODEL * DMODEL];
__device__ float g_Wv[DMODEL * DMODEL];

// ---------------- helpers ----------------
__device__ __forceinline__ unsigned f2tf32(float x) {
    unsigned u;
    asm("cvt.rna.tf32.f32 %0, %1;" : "=r"(u) : "f"(x));
    return u;
}

#define MMA_TF32(d, a, b)                                                     \
    asm volatile(                                                             \
        "mma.sync.aligned.m16n8k8.row.col.f32.tf32.tf32.f32 "                 \
        "{%0,%1,%2,%3}, {%4,%5,%6,%7}, {%8,%9}, {%0,%1,%2,%3};"               \
        : "+f"(d[0]), "+f"(d[1]), "+f"(d[2]), "+f"(d[3])                      \
        : "r"(a[0]), "r"(a[1]), "r"(a[2]), "r"(a[3]), "r"(b[0]), "r"(b[1]))

__device__ __forceinline__ float gelu_f(float v) {
    return 0.5f * v * (1.0f + erff(v * 0.70710678118654752f));
}

// ---------------- tf32x2 MMA core ----------------
// BM = 128 fixed. 256 threads = 8 warps, layout WARPS_M x WARPS_N.
// As layout: [BK/4][128][4]  (k-group, m, k-inner) -> conflict-free A frags.
// Bs layout: [BK][BN] with n ^= (k&3)*8 swizzle -> conflict-free B frags.
template<int BN, int WM, int WN, bool TRANSB>
struct MmaCore {
    static constexpr int BM = 128, BK = 16;
    static constexpr int WARPS_M = BM / WM, WARPS_N = BN / WN;
    static constexpr int MT = WM / 16, NT = WN / 8;

    __device__ static __forceinline__ void run(
        const float* __restrict__ Ag, int lda,
        const float* __restrict__ Bg, int ldb,
        int K, float (&acc)[MT][NT][4],
        float* __restrict__ As, float* __restrict__ Bs)
    {
        int t = threadIdx.x;
        int wid = t >> 5, lane = t & 31;
        int g = lane >> 2, tg = lane & 3;
        int warpM = wid / WARPS_N, warpN = wid % WARPS_N;

        #pragma unroll
        for (int mt = 0; mt < MT; mt++)
            #pragma unroll
            for (int nt = 0; nt < NT; nt++)
                #pragma unroll
                for (int i = 0; i < 4; i++) acc[mt][nt][i] = 0.f;

        for (int k0 = 0; k0 < K; k0 += BK) {
            // ---- stage A: 128x16 floats ----
            #pragma unroll
            for (int i = 0; i < 2; i++) {
                int f = t + i * 256;
                int r = f >> 2, c4 = f & 3;
                float4 v = *(const float4*)(Ag + (size_t)r * lda + k0 + c4 * 4);
                *(float4*)&As[c4 * 512 + r * 4] = v;
            }
            // ---- stage B ----
            if (!TRANSB) {
                constexpr int NB4 = (BK * BN) / 1024;  // float4 loads per thread
                #pragma unroll
                for (int i = 0; i < NB4; i++) {
                    int f = t + i * 256;
                    int r = f / (BN / 4), c4 = f % (BN / 4);
                    float4 v = *(const float4*)(Bg + (size_t)(k0 + r) * ldb + c4 * 4);
                    *(float4*)&Bs[r * BN + ((c4 * 4) ^ ((r & 3) * 8))] = v;
                }
            } else {
                // source is [n rows][k cols] row-major; Bs[k][n^swz] = src[n][k]
                #pragma unroll
                for (int i = 0; i < 2; i++) {
                    int f = t + i * 256;
                    int n = f >> 2, c4 = f & 3;
                    float4 v = *(const float4*)(Bg + (size_t)n * ldb + k0 + c4 * 4);
                    Bs[(c4 * 4 + 0) * BN + (n ^ 0 )] = v.x;
                    Bs[(c4 * 4 + 1) * BN + (n ^ 8 )] = v.y;
                    Bs[(c4 * 4 + 2) * BN + (n ^ 16)] = v.z;
                    Bs[(c4 * 4 + 3) * BN + (n ^ 24)] = v.w;
                }
            }
            __syncthreads();

            // ---- compute: two k8 steps, tf32x2 (3 MMAs each) ----
            #pragma unroll
            for (int kk = 0; kk < 2; kk++) {
                unsigned ahi[MT][4], alo[MT][4];
                #pragma unroll
                for (int mt = 0; mt < MT; mt++) {
                    int m = warpM * WM + mt * 16 + g;
                    int base = kk * 1024 + m * 4 + tg;
                    float a0 = As[base],       a1 = As[base + 32];
                    float a2 = As[base + 512], a3 = As[base + 544];
                    ahi[mt][0] = f2tf32(a0); alo[mt][0] = f2tf32(a0 - __uint_as_float(ahi[mt][0]));
                    ahi[mt][1] = f2tf32(a1); alo[mt][1] = f2tf32(a1 - __uint_as_float(ahi[mt][1]));
                    ahi[mt][2] = f2tf32(a2); alo[mt][2] = f2tf32(a2 - __uint_as_float(ahi[mt][2]));
                    ahi[mt][3] = f2tf32(a3); alo[mt][3] = f2tf32(a3 - __uint_as_float(ahi[mt][3]));
                }
                unsigned bhi[NT][2], blo[NT][2];
                int klo = kk * 8 + tg;
                #pragma unroll
                for (int nt = 0; nt < NT; nt++) {
                    int n = warpN * WN + nt * 8 + g;
                    float b0 = Bs[klo * BN + (n ^ (tg * 8))];
                    float b1 = Bs[(klo + 4) * BN + (n ^ (tg * 8))];
                    bhi[nt][0] = f2tf32(b0); blo[nt][0] = f2tf32(b0 - __uint_as_float(bhi[nt][0]));
                    bhi[nt][1] = f2tf32(b1); blo[nt][1] = f2tf32(b1 - __uint_as_float(bhi[nt][1]));
                }
                #pragma unroll
                for (int mt = 0; mt < MT; mt++)
                    #pragma unroll
                    for (int nt = 0; nt < NT; nt++) MMA_TF32(acc[mt][nt], ahi[mt], bhi[nt]);
                #pragma unroll
                for (int mt = 0; mt < MT; mt++)
                    #pragma unroll
                    for (int nt = 0; nt < NT; nt++) MMA_TF32(acc[mt][nt], alo[mt], bhi[nt]);
                #pragma unroll
                for (int mt = 0; mt < MT; mt++)
                    #pragma unroll
                    for (int nt = 0; nt < NT; nt++) MMA_TF32(acc[mt][nt], ahi[mt], blo[nt]);
            }
            __syncthreads();
        }
    }
};

// ---------------- linear GEMM: C = A[M,K] @ B[K,N] (+bias/gelu/resid) ----------------
template<bool BIAS, bool GELU, bool RESID>
__global__ void __launch_bounds__(256) linear_mma(
    const float* __restrict__ A, const float* __restrict__ B,
    const float* __restrict__ bias, const float* __restrict__ resid,
    float* __restrict__ C, int M, int N, int K)
{
    using Core = MmaCore<128, 64, 32, false>;
    __shared__ float As[2048];
    __shared__ float Bs[16 * 128];
    const float* Ag = A + (size_t)blockIdx.y * 128 * K;
    const float* Bg = B + blockIdx.x * 128;
    float acc[Core::MT][Core::NT][4];
    Core::run(Ag, K, Bg, N, K, acc, As, Bs);

    int t = threadIdx.x, wid = t >> 5, lane = t & 31;
    int g = lane >> 2, tg = lane & 3;
    int warpM = wid / Core::WARPS_N, warpN = wid % Core::WARPS_N;
    int row0 = blockIdx.y * 128 + warpM * 64;
    int col0 = blockIdx.x * 128 + warpN * 32;
    #pragma unroll
    for (int mt = 0; mt < Core::MT; mt++) {
        int row = row0 + mt * 16 + g;
        #pragma unroll
        for (int nt = 0; nt < Core::NT; nt++) {
            int col = col0 + nt * 8 + tg * 2;
            float v0 = acc[mt][nt][0], v1 = acc[mt][nt][1];
            float v2 = acc[mt][nt][2], v3 = acc[mt][nt][3];
            if (BIAS) {
                float b0 = bias[col], b1 = bias[col + 1];
                v0 += b0; v1 += b1; v2 += b0; v3 += b1;
            }
            if (GELU) { v0 = gelu_f(v0); v1 = gelu_f(v1); v2 = gelu_f(v2); v3 = gelu_f(v3); }
            if (RESID) {
                float2 r0 = *(const float2*)(resid + (size_t)row * N + col);
                float2 r1 = *(const float2*)(resid + (size_t)(row + 8) * N + col);
                v0 += r0.x; v1 += r0.y; v2 += r1.x; v3 += r1.y;
            }
            *(float2*)(C + (size_t)row * N + col) = make_float2(v0, v1);
            *(float2*)(C + (size_t)(row + 8) * N + col) = make_float2(v2, v3);
        }
    }
}

// ---------------- scores: S[q,k] = (K_q . Q_k) / 8, per (b,h) ----------------
__global__ void __launch_bounds__(256) score_mma(
    const float* __restrict__ Kmat, const float* __restrict__ Qmat,
    float* __restrict__ S)
{
    using Core = MmaCore<128, 64, 32, true>;
    __shared__ float As[2048];
    __shared__ float Bs[16 * 128];
    int bh = blockIdx.z, b = bh >> 4, h = bh & 15;
    const float* Ag = Kmat + (size_t)b * TLEN * DMODEL + h * HP + (size_t)blockIdx.y * 128 * DMODEL;
    const float* Bg = Qmat + (size_t)b * TLEN * DMODEL + h * HP + (size_t)blockIdx.x * 128 * DMODEL;
    float* Sb = S + (size_t)bh * TLEN * TLEN;
    float acc[Core::MT][Core::NT][4];
    Core::run(Ag, DMODEL, Bg, DMODEL, HP, acc, As, Bs);

    int t = threadIdx.x, wid = t >> 5, lane = t & 31;
    int g = lane >> 2, tg = lane & 3;
    int warpM = wid / Core::WARPS_N, warpN = wid % Core::WARPS_N;
    int row0 = blockIdx.y * 128 + warpM * 64;
    int col0 = blockIdx.x * 128 + warpN * 32;
    #pragma unroll
    for (int mt = 0; mt < Core::MT; mt++) {
        int row = row0 + mt * 16 + g;
        #pragma unroll
        for (int nt = 0; nt < Core::NT; nt++) {
            int col = col0 + nt * 8 + tg * 2;
            *(float2*)(Sb + (size_t)row * TLEN + col) =
                make_float2(acc[mt][nt][0] * 0.125f, acc[mt][nt][1] * 0.125f);
            *(float2*)(Sb + (size_t)(row + 8) * TLEN + col) =
                make_float2(acc[mt][nt][2] * 0.125f, acc[mt][nt][3] * 0.125f);
        }
    }
}

// ---------------- AV: nv[q,p] = sum_k attn[q,k] V[k,p], per (b,h) ----------------
__global__ void __launch_bounds__(256) av_mma(
    const float* __restrict__ Attn, const float* __restrict__ V,
    float* __restrict__ O)
{
    using Core = MmaCore<64, 32, 32, false>;
    __shared__ float As[2048];
    __shared__ float Bs[16 * 64];
    int bh = blockIdx.z, b = bh >> 4, h = bh & 15;
    const float* Ag = Attn + (size_t)bh * TLEN * TLEN + (size_t)blockIdx.x * 128 * TLEN;
    const float* Bg = V + (size_t)b * TLEN * DMODEL + h * HP;
    float* Ob = O + (size_t)b * TLEN * DMODEL + h * HP + (size_t)blockIdx.x * 128 * DMODEL;
    float acc[Core::MT][Core::NT][4];
    Core::run(Ag, TLEN, Bg, DMODEL, TLEN, acc, As, Bs);

    int t = threadIdx.x, wid = t >> 5, lane = t & 31;
    int g = lane >> 2, tg = lane & 3;
    int warpM = wid / Core::WARPS_N, warpN = wid % Core::WARPS_N;
    int row0 = warpM * 32;
    int col0 = warpN * 32;
    #pragma unroll
    for (int mt = 0; mt < Core::MT; mt++) {
        int row = row0 + mt * 16 + g;
        #pragma unroll
        for (int nt = 0; nt < Core::NT; nt++) {
            int col = col0 + nt * 8 + tg * 2;
            *(float2*)(Ob + (size_t)row * DMODEL + col) =
                make_float2(acc[mt][nt][0], acc[mt][nt][1]);
            *(float2*)(Ob + (size_t)(row + 8) * DMODEL + col) =
                make_float2(acc[mt][nt][2], acc[mt][nt][3]);
        }
    }
}

// ---------------- LayerNorm (one block per row of 1024) ----------------
__global__ void __launch_bounds__(256) ln_kernel(
    const float* __restrict__ x, const float* __restrict__ g,
    const float* __restrict__ b, const float* __restrict__ resid,
    float* __restrict__ out)
{
    int row = blockIdx.x;
    int t = threadIdx.x;
    const float4* xr = (const float4*)(x + (size_t)row * DMODEL);
    float4 v = xr[t];
    float s  = v.x + v.y + v.z + v.w;
    float s2 = v.x*v.x + v.y*v.y + v.z*v.z + v.w*v.w;
    #pragma unroll
    for (int o = 16; o > 0; o >>= 1) {
        s  += __shfl_xor_sync(0xffffffffu, s,  o);
        s2 += __shfl_xor_sync(0xffffffffu, s2, o);
    }
    __shared__ float shs[8], shs2[8];
    __shared__ float mean_s, rstd_s;
    int wid = t >> 5, lane = t & 31;
    if (lane == 0) { shs[wid] = s; shs2[wid] = s2; }
    __syncthreads();
    if (t == 0) {
        float ts = 0.f, ts2 = 0.f;
        #pragma unroll
        for (int i = 0; i < 8; i++) { ts += shs[i]; ts2 += shs2[i]; }
        float mean = ts * (1.0f / DMODEL);
        float var  = ts2 * (1.0f / DMODEL) - mean * mean;
        mean_s = mean;
        rstd_s = rsqrtf(var + 1e-5f);
    }
    __syncthreads();
    float m = mean_s, r = rstd_s;
    float4 gv = ((const float4*)g)[t];
    float4 bv = ((const float4*)b)[t];
    float4 o;
    o.x = (v.x - m) * r * gv.x + bv.x;
    o.y = (v.y - m) * r * gv.y + bv.y;
    o.z = (v.z - m) * r * gv.z + bv.z;
    o.w = (v.w - m) * r * gv.w + bv.w;
    if (resid) {
        float4 rv = ((const float4*)(resid + (size_t)row * DMODEL))[t];
        o.x += rv.x; o.y += rv.y; o.z += rv.z; o.w += rv.w;
    }
    ((float4*)(out + (size_t)row * DMODEL))[t] = o;
}

// ---------------- weight transpose: (h,d,p) -> (d, h*P+p) ----------------
__global__ void transpose_w(const float* __restrict__ in, float* __restrict__ out)
{
    int idx = blockIdx.x * blockDim.x + threadIdx.x;
    if (idx >= DMODEL * DMODEL) return;
    int p = idx & (HP - 1);
    int d = (idx >> 6) & (DMODEL - 1);
    int h = idx >> 16;
    out[d * DMODEL + h * HP + p] = in[idx];
}

// ---------------- row softmax over 2048 (in-place) ----------------
__global__ void __launch_bounds__(256) softmax_kernel(float* __restrict__ S)
{
    size_t row = blockIdx.x;
    float* r = S + row * (size_t)TLEN;
    int t = threadIdx.x;
    float4 v0 = ((float4*)r)[t];
    float4 v1 = ((float4*)r)[t + 256];
    float mx = fmaxf(fmaxf(fmaxf(v0.x, v0.y), fmaxf(v0.z, v0.w)),
                     fmaxf(fmaxf(v1.x, v1.y), fmaxf(v1.z, v1.w)));
    #pragma unroll
    for (int o = 16; o > 0; o >>= 1) mx = fmaxf(mx, __shfl_xor_sync(0xffffffffu, mx, o));
    __shared__ float sm[8];
    __shared__ float mx_s, inv_s;
    int wid = t >> 5, lane = t & 31;
    if (lane == 0) sm[wid] = mx;
    __syncthreads();
    if (t == 0) {
        float m = sm[0];
        #pragma unroll
        for (int i = 1; i < 8; i++) m = fmaxf(m, sm[i]);
        mx_s = m;
    }
    __syncthreads();
    float m = mx_s;
    v0.x = __expf(v0.x - m); v0.y = __expf(v0.y - m);
    v0.z = __expf(v0.z - m); v0.w = __expf(v0.w - m);
    v1.x = __expf(v1.x - m); v1.y = __expf(v1.y - m);
    v1.z = __expf(v1.z - m); v1.w = __expf(v1.w - m);
    float s = v0.x + v0.y + v0.z + v0.w + v1.x + v1.y + v1.z + v1.w;
    #pragma unroll
    for (int o = 16; o > 0; o >>= 1) s += __shfl_xor_sync(0xffffffffu, s, o);
    if (lane == 0) sm[wid] = s;
    __syncthreads();
    if (t == 0) {
        float ts = 0.f;
        #pragma unroll
        for (int i = 0; i < 8; i++) ts += sm[i];
        inv_s = 1.0f / ts;
    }
    __syncthreads();
    float inv = inv_s;
    v0.x *= inv; v0.y *= inv; v0.z *= inv; v0.w *= inv;
    v1.x *= inv; v1.y *= inv; v1.z *= inv; v1.w *= inv;
    ((float4*)r)[t] = v0;
    ((float4*)r)[t + 256] = v1;
}

// ---------------- launch ----------------
extern "C" void kernel_launch(void* const* d_in, const int* in_sizes, int n_in,
                              void* d_out, int out_size)
{
    const float* X      = (const float*)d_in[0];
    const float* WQ     = (const float*)d_in[1];
    const float* WK     = (const float*)d_in[2];
    const float* WV     = (const float*)d_in[3];
    const float* WO     = (const float*)d_in[4];
    const float* attn_g = (const float*)d_in[5];
    const float* attn_b = (const float*)d_in[6];
    const float* ff_g   = (const float*)d_in[7];
    const float* ff_b   = (const float*)d_in[8];
    const float* fW1    = (const float*)d_in[9];
    const float* fb1    = (const float*)d_in[10];
    const float* fW2    = (const float*)d_in[11];
    const float* fb2    = (const float*)d_in[12];

    float* out  = (float*)d_out;
    float* attn = out + (size_t)NTOK * DMODEL;   // [B,H,T,T]

    float *nX, *Q, *K, *V, *nv, *ss, *preff, *hidden, *Wq, *Wk, *Wv;
    cudaGetSymbolAddress((void**)&nX,     g_nX);
    cudaGetSymbolAddress((void**)&Q,      g_Q);
    cudaGetSymbolAddress((void**)&K,      g_Kt);
    cudaGetSymbolAddress((void**)&V,      g_V);
    cudaGetSymbolAddress((void**)&nv,     g_nv);
    cudaGetSymbolAddress((void**)&ss,     g_ss);
    cudaGetSymbolAddress((void**)&preff,  g_preff);
    cudaGetSymbolAddress((void**)&hidden, g_hidden);
    cudaGetSymbolAddress((void**)&Wq,     g_Wq);
    cudaGetSymbolAddress((void**)&Wk,     g_Wk);
    cudaGetSymbolAddress((void**)&Wv,     g_Wv);

    // 1. nX = LN(X)
    ln_kernel<<<NTOK, 256>>>(X, attn_g, attn_b, nullptr, nX);

    // 2. transpose weights: (h,d,p) -> (d, h*P+p)
    transpose_w<<<4096, 256>>>(WQ, Wq);
    transpose_w<<<4096, 256>>>(WK, Wk);
    transpose_w<<<4096, 256>>>(WV, Wv);

    // 3. Q/K/V projections (tf32x2 tensor core)
    dim3 gQKV(DMODEL / 128, NTOK / 128);
    linear_mma<false, false, false><<<gQKV, 256>>>(nX, Wq, nullptr, nullptr, Q, NTOK, DMODEL, DMODEL);
    linear_mma<false, false, false><<<gQKV, 256>>>(nX, Wk, nullptr, nullptr, K, NTOK, DMODEL, DMODEL);
    linear_mma<false, false, false><<<gQKV, 256>>>(nX, Wv, nullptr, nullptr, V, NTOK, DMODEL, DMODEL);

    // 4. scores -> attn buffer; 5. softmax in-place; 6. nv = attn @ V
    score_mma<<<dim3(TLEN / 128, TLEN / 128, BATCH * NH), 256>>>(K, Q, attn);
    softmax_kernel<<<BATCH * NH * TLEN, 256>>>(attn);
    av_mma<<<dim3(TLEN / 128, 1, BATCH * NH), 256>>>(attn, V, nv);

    // 7. seq_summary = nv @ WO  (WO already [H*P, D] contiguous)
    linear_mma<false, false, false><<<gQKV, 256>>>(nv, WO, nullptr, nullptr, ss, NTOK, DMODEL, DMODEL);

    // 8. pre_ff = X + LN(ss)
    ln_kernel<<<NTOK, 256>>>(ss, ff_g, ff_b, X, preff);

    // 9. hidden = gelu(pre_ff @ fW1 + fb1)
    linear_mma<true, true, false><<<dim3(FFDIM / 128, NTOK / 128), 256>>>(
        preff, fW1, fb1, nullptr, hidden, NTOK, FFDIM, DMODEL);

    // 10. out = hidden @ fW2 + fb2 + pre_ff
    linear_mma<true, false, true><<<dim3(DMODEL / 128, NTOK / 128), 256>>>(
        hidden, fW2, fb2, preff, out, NTOK, DMODEL, FFDIM);
}

// round 11
// speedup vs baseline: 2.0787x; 1.9908x over previous
#include <cuda_runtime.h>
#include <cstdint>
#include <math.h>

#define BATCH 4
#define TLEN 2048
#define DMODEL 1024
#define NH 16
#define HP 64
#define FFDIM 4096
#define NTOK (BATCH * TLEN)   // 8192

// ---------------- scratch (static __device__, allocation-free) ----------------
__device__ float g_nX   [(size_t)NTOK * DMODEL];
__device__ float g_Q    [(size_t)NTOK * DMODEL];
__device__ float g_Kb   [(size_t)NTOK * DMODEL];
__device__ float g_V    [(size_t)NTOK * DMODEL];
__device__ float g_Vt   [(size_t)NTOK * DMODEL];      // [b,h,p,t]
__device__ float g_nv   [(size_t)NTOK * DMODEL];
__device__ float g_ss   [(size_t)NTOK * DMODEL];
__device__ float g_preff[(size_t)NTOK * DMODEL];
__device__ float g_hidden[(size_t)NTOK * FFDIM];
__device__ float g_Wq [DMODEL * DMODEL];               // [h*P+p, d]  (K-major)
__device__ float g_Wk [DMODEL * DMODEL];
__device__ float g_Wv [DMODEL * DMODEL];
__device__ float g_Wot[DMODEL * DMODEL];               // [d, h*P+p]
__device__ float g_W1t[(size_t)DMODEL * FFDIM];        // [ff, d]
__device__ float g_W2t[(size_t)DMODEL * FFDIM];        // [d, ff]

// ---------------- helpers ----------------
__device__ __forceinline__ uint32_t packbf(float lo, float hi) {
    // low 16 bits = bf16(lo), high 16 = bf16(hi)
    uint32_t u;
    asm("cvt.rn.bf16x2.f32 %0, %1, %2;" : "=r"(u) : "f"(hi), "f"(lo));
    return u;
}
__device__ __forceinline__ float lo_f(uint32_t u) { return __uint_as_float(u << 16); }
__device__ __forceinline__ float hi_f(uint32_t u) { return __uint_as_float(u & 0xFFFF0000u); }

#define MMA_BF16(d, a, b)                                                     \
    asm volatile(                                                             \
        "mma.sync.aligned.m16n8k16.row.col.f32.bf16.bf16.f32 "               \
        "{%0,%1,%2,%3}, {%4,%5,%6,%7}, {%8,%9}, {%0,%1,%2,%3};"               \
        : "+f"(d[0]), "+f"(d[1]), "+f"(d[2]), "+f"(d[3])                      \
        : "r"(a[0]), "r"(a[1]), "r"(a[2]), "r"(a[3]), "r"(b[0]), "r"(b[1]))

__device__ __forceinline__ float gelu_f(float v) {
    return 0.5f * v * (1.0f + erff(v * 0.70710678118654752f));
}

// ---------------- bf16x2-split mma core ----------------
// BM=128, BK=32 (16 k-pairs). A: [128,K] row-major; B: [BN,K] row-major (K-major).
// SMEM planes per stage (uint32): Ah[16][132], Al, Bh[16][BN+4], Bl.
// Double-buffered: gmem prefetch -> regs, convert+store after mma, 1 sync/tile.
template<int BN, int WARPS_M, int WARPS_N>
struct Core {
    static constexpr int BM = 128, KP = 16;       // k-pairs per tile (BK=32)
    static constexpr int WM = BM / WARPS_M, WN = BN / WARPS_N;
    static constexpr int MT = WM / 16, NT = WN / 8;
    static constexpr int AP = BM + 4, BP = BN + 4;
    static constexpr int ASZ = KP * AP, BSZ = KP * BP;
    static constexpr int STG = 2 * ASZ + 2 * BSZ; // uint32 per stage
    static constexpr int NA = 4, NB = BN / 32;    // float4 loads per thread

    __device__ static __forceinline__ void cvt_store(
        uint32_t* __restrict__ H, uint32_t* __restrict__ L,
        int c, int r, int P, float4 v)
    {
        uint32_t h01 = packbf(v.x, v.y);
        uint32_t h23 = packbf(v.z, v.w);
        float r0 = v.x - lo_f(h01), r1 = v.y - hi_f(h01);
        float r2 = v.z - lo_f(h23), r3 = v.w - hi_f(h23);
        H[(2 * c)     * P + r] = h01;
        H[(2 * c + 1) * P + r] = h23;
        L[(2 * c)     * P + r] = packbf(r0, r1);
        L[(2 * c + 1) * P + r] = packbf(r2, r3);
    }

    __device__ static __forceinline__ void stage_to(
        uint32_t* st, const float4* pa, const float4* pb, int t)
    {
        uint32_t* Ah = st;
        uint32_t* Al = st + ASZ;
        uint32_t* Bh = Al + ASZ;
        uint32_t* Bl = Bh + BSZ;
        #pragma unroll
        for (int i = 0; i < NA; i++) {
            int f = t + i * 256;
            cvt_store(Ah, Al, f & 7, f >> 3, AP, pa[i]);
        }
        #pragma unroll
        for (int i = 0; i < NB; i++) {
            int f = t + i * 256;
            cvt_store(Bh, Bl, f & 7, f >> 3, BP, pb[i]);
        }
    }

    __device__ static __forceinline__ void run(
        const float* __restrict__ Ag, int lda,
        const float* __restrict__ Bg, int ldb, int K,
        uint32_t* sm, float (&acc)[MT][NT][4])
    {
        const int t = threadIdx.x, lane = t & 31, wid = t >> 5;
        const int g = lane >> 2, tg = lane & 3;
        const int warpM = wid / WARPS_N, warpN = wid % WARPS_N;

        #pragma unroll
        for (int mt = 0; mt < MT; mt++)
            #pragma unroll
            for (int nt = 0; nt < NT; nt++)
                #pragma unroll
                for (int i = 0; i < 4; i++) acc[mt][nt][i] = 0.f;

        const int KT = K >> 5;
        float4 pa[NA], pb[NB];

        // preload tile 0
        #pragma unroll
        for (int i = 0; i < NA; i++) {
            int f = t + i * 256;
            pa[i] = *(const float4*)(Ag + (size_t)(f >> 3) * lda + (f & 7) * 4);
        }
        #pragma unroll
        for (int i = 0; i < NB; i++) {
            int f = t + i * 256;
            pb[i] = *(const float4*)(Bg + (size_t)(f >> 3) * ldb + (f & 7) * 4);
        }
        stage_to(sm, pa, pb, t);
        __syncthreads();

        for (int kt = 0; kt < KT; kt++) {
            int s = kt & 1;
            if (kt + 1 < KT) {
                int k0 = (kt + 1) << 5;
                #pragma unroll
                for (int i = 0; i < NA; i++) {
                    int f = t + i * 256;
                    pa[i] = *(const float4*)(Ag + (size_t)(f >> 3) * lda + k0 + (f & 7) * 4);
                }
                #pragma unroll
                for (int i = 0; i < NB; i++) {
                    int f = t + i * 256;
                    pb[i] = *(const float4*)(Bg + (size_t)(f >> 3) * ldb + k0 + (f & 7) * 4);
                }
            }
            uint32_t* Ah = sm + s * STG;
            uint32_t* Al = Ah + ASZ;
            uint32_t* Bh = Al + ASZ;
            uint32_t* Bl = Bh + BSZ;
            #pragma unroll
            for (int ks = 0; ks < 2; ks++) {
                int kb = ks * 8;
                uint32_t ahi[MT][4], alo[MT][4], bhi[NT][2], blo[NT][2];
                #pragma unroll
                for (int mt = 0; mt < MT; mt++) {
                    int m = warpM * WM + mt * 16 + g;
                    int i0 = (kb + tg) * AP + m;
                    int i1 = (kb + tg + 4) * AP + m;
                    ahi[mt][0] = Ah[i0]; ahi[mt][1] = Ah[i0 + 8];
                    ahi[mt][2] = Ah[i1]; ahi[mt][3] = Ah[i1 + 8];
                    alo[mt][0] = Al[i0]; alo[mt][1] = Al[i0 + 8];
                    alo[mt][2] = Al[i1]; alo[mt][3] = Al[i1 + 8];
                }
                #pragma unroll
                for (int nt = 0; nt < NT; nt++) {
                    int n = warpN * WN + nt * 8 + g;
                    int j0 = (kb + tg) * BP + n;
                    int j1 = (kb + tg + 4) * BP + n;
                    bhi[nt][0] = Bh[j0]; bhi[nt][1] = Bh[j1];
                    blo[nt][0] = Bl[j0]; blo[nt][1] = Bl[j1];
                }
                #pragma unroll
                for (int mt = 0; mt < MT; mt++)
                    #pragma unroll
                    for (int nt = 0; nt < NT; nt++) MMA_BF16(acc[mt][nt], ahi[mt], bhi[nt]);
                #pragma unroll
                for (int mt = 0; mt < MT; mt++)
                    #pragma unroll
                    for (int nt = 0; nt < NT; nt++) MMA_BF16(acc[mt][nt], ahi[mt], blo[nt]);
                #pragma unroll
                for (int mt = 0; mt < MT; mt++)
                    #pragma unroll
                    for (int nt = 0; nt < NT; nt++) MMA_BF16(acc[mt][nt], alo[mt], bhi[nt]);
            }
            if (kt + 1 < KT) stage_to(sm + (s ^ 1) * STG, pa, pb, t);
            __syncthreads();
        }
    }
};

// ---------------- linear: C[M,N] = A[M,K] @ Bt[N,K]^T (+bias/gelu/resid) ----------------
template<bool BIAS, bool GELU, bool RESID>
__global__ void __launch_bounds__(256, 1) linear_bf(
    const float* __restrict__ A, const float* __restrict__ Bt,
    const float* __restrict__ bias, const float* __restrict__ resid,
    float* __restrict__ C, int N, int K)
{
    using Co = Core<128, 2, 4>;
    extern __shared__ uint32_t sm[];
    float acc[Co::MT][Co::NT][4];
    Co::run(A + (size_t)blockIdx.y * 128 * K, K,
            Bt + (size_t)blockIdx.x * 128 * K, K, K, sm, acc);

    int t = threadIdx.x, lane = t & 31, wid = t >> 5;
    int g = lane >> 2, tg = lane & 3;
    int warpM = wid / 4, warpN = wid % 4;
    int row0 = blockIdx.y * 128 + warpM * Co::WM;
    int col0 = blockIdx.x * 128 + warpN * Co::WN;
    #pragma unroll
    for (int mt = 0; mt < Co::MT; mt++) {
        int row = row0 + mt * 16 + g;
        #pragma unroll
        for (int nt = 0; nt < Co::NT; nt++) {
            int col = col0 + nt * 8 + tg * 2;
            float v0 = acc[mt][nt][0], v1 = acc[mt][nt][1];
            float v2 = acc[mt][nt][2], v3 = acc[mt][nt][3];
            if (BIAS) {
                float b0 = bias[col], b1 = bias[col + 1];
                v0 += b0; v1 += b1; v2 += b0; v3 += b1;
            }
            if (GELU) { v0 = gelu_f(v0); v1 = gelu_f(v1); v2 = gelu_f(v2); v3 = gelu_f(v3); }
            if (RESID) {
                float2 r0 = *(const float2*)(resid + (size_t)row * N + col);
                float2 r1 = *(const float2*)(resid + (size_t)(row + 8) * N + col);
                v0 += r0.x; v1 += r0.y; v2 += r1.x; v3 += r1.y;
            }
            *(float2*)(C + (size_t)row * N + col) = make_float2(v0, v1);
            *(float2*)(C + (size_t)(row + 8) * N + col) = make_float2(v2, v3);
        }
    }
}

// ---------------- scores: S[q,k] = (K_q . Q_k)/8 per (b,h) ----------------
__global__ void __launch_bounds__(256, 1) score_bf(
    const float* __restrict__ Kbuf, const float* __restrict__ Qbuf,
    float* __restrict__ S)
{
    using Co = Core<128, 2, 4>;
    extern __shared__ uint32_t sm[];
    int bh = blockIdx.z, b = bh >> 4, h = bh & 15;
    float acc[Co::MT][Co::NT][4];
    Co::run(Kbuf + (size_t)b * TLEN * DMODEL + h * HP + (size_t)blockIdx.y * 128 * DMODEL, DMODEL,
            Qbuf + (size_t)b * TLEN * DMODEL + h * HP + (size_t)blockIdx.x * 128 * DMODEL, DMODEL,
            HP, sm, acc);

    int t = threadIdx.x, lane = t & 31, wid = t >> 5;
    int g = lane >> 2, tg = lane & 3;
    int warpM = wid / 4, warpN = wid % 4;
    float* Sb = S + (size_t)bh * TLEN * TLEN;
    int row0 = blockIdx.y * 128 + warpM * Co::WM;
    int col0 = blockIdx.x * 128 + warpN * Co::WN;
    #pragma unroll
    for (int mt = 0; mt < Co::MT; mt++) {
        int row = row0 + mt * 16 + g;
        #pragma unroll
        for (int nt = 0; nt < Co::NT; nt++) {
            int col = col0 + nt * 8 + tg * 2;
            *(float2*)(Sb + (size_t)row * TLEN + col) =
                make_float2(acc[mt][nt][0] * 0.125f, acc[mt][nt][1] * 0.125f);
            *(float2*)(Sb + (size_t)(row + 8) * TLEN + col) =
                make_float2(acc[mt][nt][2] * 0.125f, acc[mt][nt][3] * 0.125f);
        }
    }
}

// ---------------- AV: nv[q,p] = sum_t attn[q,t] Vt[p,t] per (b,h) ----------------
__global__ void __launch_bounds__(256, 1) av_bf(
    const float* __restrict__ Attn, const float* __restrict__ Vt,
    float* __restrict__ O)
{
    using Co = Core<64, 4, 2>;
    extern __shared__ uint32_t sm[];
    int bh = blockIdx.z, b = bh >> 4, h = bh & 15;
    float acc[Co::MT][Co::NT][4];
    Co::run(Attn + (size_t)bh * TLEN * TLEN + (size_t)blockIdx.x * 128 * TLEN, TLEN,
            Vt + (size_t)bh * HP * TLEN, TLEN, TLEN, sm, acc);

    int t = threadIdx.x, lane = t & 31, wid = t >> 5;
    int g = lane >> 2, tg = lane & 3;
    int warpM = wid / 2, warpN = wid % 2;
    #pragma unroll
    for (int mt = 0; mt < Co::MT; mt++) {
        int row = warpM * Co::WM + mt * 16 + g;
        float* Crow = O + ((size_t)b * TLEN + blockIdx.x * 128 + row) * DMODEL + h * HP;
        #pragma unroll
        for (int nt = 0; nt < Co::NT; nt++) {
            int col = warpN * Co::WN + nt * 8 + tg * 2;
            *(float2*)(Crow + col) = make_float2(acc[mt][nt][0], acc[mt][nt][1]);
            *(float2*)(Crow + 8 * DMODEL + col) = make_float2(acc[mt][nt][2], acc[mt][nt][3]);
        }
    }
}

// ---------------- tiled transpose: out[C,R] = in[R,C]^T, batched ----------------
__global__ void transpose_tiled(const float* __restrict__ in, float* __restrict__ out,
                                int R, int C, long long inBS, long long outBS)
{
    __shared__ float tile[32][33];
    const float* I = in + (size_t)blockIdx.z * inBS;
    float* Ot = out + (size_t)blockIdx.z * outBS;
    int c0 = blockIdx.x * 32, r0 = blockIdx.y * 32;
    int tx = threadIdx.x, ty = threadIdx.y;
    #pragma unroll
    for (int j = 0; j < 32; j += 8)
        tile[ty + j][tx] = I[(size_t)(r0 + ty + j) * C + c0 + tx];
    __syncthreads();
    #pragma unroll
    for (int j = 0; j < 32; j += 8)
        Ot[(size_t)(c0 + ty + j) * R + r0 + tx] = tile[tx][ty + j];
}

// ---------------- V transpose: Vt[b,h,p,t] = V[b,t,h*64+p] ----------------
__global__ void vt_kernel(const float* __restrict__ V, float* __restrict__ Vt)
{
    __shared__ float tile[32][33];
    int bh = blockIdx.z, b = bh >> 4, h = bh & 15;
    int t0 = blockIdx.x * 32, p0 = blockIdx.y * 32;
    int tx = threadIdx.x, ty = threadIdx.y;
    const float* I = V + (size_t)b * TLEN * DMODEL + h * HP;
    #pragma unroll
    for (int j = 0; j < 32; j += 8)
        tile[ty + j][tx] = I[(size_t)(t0 + ty + j) * DMODEL + p0 + tx];
    __syncthreads();
    float* O = Vt + (size_t)bh * HP * TLEN;
    #pragma unroll
    for (int j = 0; j < 32; j += 8)
        O[(size_t)(p0 + ty + j) * TLEN + t0 + tx] = tile[tx][ty + j];
}

// ---------------- LayerNorm (one block per row of 1024) ----------------
__global__ void __launch_bounds__(256) ln_kernel(
    const float* __restrict__ x, const float* __restrict__ g,
    const float* __restrict__ b, const float* __restrict__ resid,
    float* __restrict__ out)
{
    int row = blockIdx.x;
    int t = threadIdx.x;
    const float4* xr = (const float4*)(x + (size_t)row * DMODEL);
    float4 v = xr[t];
    float s  = v.x + v.y + v.z + v.w;
    float s2 = v.x*v.x + v.y*v.y + v.z*v.z + v.w*v.w;
    #pragma unroll
    for (int o = 16; o > 0; o >>= 1) {
        s  += __shfl_xor_sync(0xffffffffu, s,  o);
        s2 += __shfl_xor_sync(0xffffffffu, s2, o);
    }
    __shared__ float shs[8], shs2[8];
    __shared__ float mean_s, rstd_s;
    int wid = t >> 5, lane = t & 31;
    if (lane == 0) { shs[wid] = s; shs2[wid] = s2; }
    __syncthreads();
    if (t == 0) {
        float ts = 0.f, ts2 = 0.f;
        #pragma unroll
        for (int i = 0; i < 8; i++) { ts += shs[i]; ts2 += shs2[i]; }
        float mean = ts * (1.0f / DMODEL);
        float var  = ts2 * (1.0f / DMODEL) - mean * mean;
        mean_s = mean;
        rstd_s = rsqrtf(var + 1e-5f);
    }
    __syncthreads();
    float m = mean_s, r = rstd_s;
    float4 gv = ((const float4*)g)[t];
    float4 bv = ((const float4*)b)[t];
    float4 o;
    o.x = (v.x - m) * r * gv.x + bv.x;
    o.y = (v.y - m) * r * gv.y + bv.y;
    o.z = (v.z - m) * r * gv.z + bv.z;
    o.w = (v.w - m) * r * gv.w + bv.w;
    if (resid) {
        float4 rv = ((const float4*)(resid + (size_t)row * DMODEL))[t];
        o.x += rv.x; o.y += rv.y; o.z += rv.z; o.w += rv.w;
    }
    ((float4*)(out + (size_t)row * DMODEL))[t] = o;
}

// ---------------- row softmax over 2048 (in-place) ----------------
__global__ void __launch_bounds__(256) softmax_kernel(float* __restrict__ S)
{
    size_t row = blockIdx.x;
    float* r = S + row * (size_t)TLEN;
    int t = threadIdx.x;
    float4 v0 = ((float4*)r)[t];
    float4 v1 = ((float4*)r)[t + 256];
    float mx = fmaxf(fmaxf(fmaxf(v0.x, v0.y), fmaxf(v0.z, v0.w)),
                     fmaxf(fmaxf(v1.x, v1.y), fmaxf(v1.z, v1.w)));
    #pragma unroll
    for (int o = 16; o > 0; o >>= 1) mx = fmaxf(mx, __shfl_xor_sync(0xffffffffu, mx, o));
    __shared__ float sm[8];
    __shared__ float mx_s, inv_s;
    int wid = t >> 5, lane = t & 31;
    if (lane == 0) sm[wid] = mx;
    __syncthreads();
    if (t == 0) {
        float m = sm[0];
        #pragma unroll
        for (int i = 1; i < 8; i++) m = fmaxf(m, sm[i]);
        mx_s = m;
    }
    __syncthreads();
    float m = mx_s;
    v0.x = __expf(v0.x - m); v0.y = __expf(v0.y - m);
    v0.z = __expf(v0.z - m); v0.w = __expf(v0.w - m);
    v1.x = __expf(v1.x - m); v1.y = __expf(v1.y - m);
    v1.z = __expf(v1.z - m); v1.w = __expf(v1.w - m);
    float s = v0.x + v0.y + v0.z + v0.w + v1.x + v1.y + v1.z + v1.w;
    #pragma unroll
    for (int o = 16; o > 0; o >>= 1) s += __shfl_xor_sync(0xffffffffu, s, o);
    if (lane == 0) sm[wid] = s;
    __syncthreads();
    if (t == 0) {
        float ts = 0.f;
        #pragma unroll
        for (int i = 0; i < 8; i++) ts += sm[i];
        inv_s = 1.0f / ts;
    }
    __syncthreads();
    float inv = inv_s;
    v0.x *= inv; v0.y *= inv; v0.z *= inv; v0.w *= inv;
    v1.x *= inv; v1.y *= inv; v1.z *= inv; v1.w *= inv;
    ((float4*)r)[t] = v0;
    ((float4*)r)[t + 256] = v1;
}

// ---------------- launch ----------------
extern "C" void kernel_launch(void* const* d_in, const int* in_sizes, int n_in,
                              void* d_out, int out_size)
{
    const float* X      = (const float*)d_in[0];
    const float* WQ     = (const float*)d_in[1];
    const float* WK     = (const float*)d_in[2];
    const float* WV     = (const float*)d_in[3];
    const float* WO     = (const float*)d_in[4];
    const float* attn_g = (const float*)d_in[5];
    const float* attn_b = (const float*)d_in[6];
    const float* ff_g   = (const float*)d_in[7];
    const float* ff_b   = (const float*)d_in[8];
    const float* fW1    = (const float*)d_in[9];
    const float* fb1    = (const float*)d_in[10];
    const float* fW2    = (const float*)d_in[11];
    const float* fb2    = (const float*)d_in[12];

    float* out  = (float*)d_out;
    float* attn = out + (size_t)NTOK * DMODEL;   // [B,H,T,T]

    float *nX, *Q, *K, *V, *Vt, *nv, *ss, *preff, *hidden;
    float *Wq, *Wk, *Wv, *Wot, *W1t, *W2t;
    cudaGetSymbolAddress((void**)&nX,     g_nX);
    cudaGetSymbolAddress((void**)&Q,      g_Q);
    cudaGetSymbolAddress((void**)&K,      g_Kb);
    cudaGetSymbolAddress((void**)&V,      g_V);
    cudaGetSymbolAddress((void**)&Vt,     g_Vt);
    cudaGetSymbolAddress((void**)&nv,     g_nv);
    cudaGetSymbolAddress((void**)&ss,     g_ss);
    cudaGetSymbolAddress((void**)&preff,  g_preff);
    cudaGetSymbolAddress((void**)&hidden, g_hidden);
    cudaGetSymbolAddress((void**)&Wq,     g_Wq);
    cudaGetSymbolAddress((void**)&Wk,     g_Wk);
    cudaGetSymbolAddress((void**)&Wv,     g_Wv);
    cudaGetSymbolAddress((void**)&Wot,    g_Wot);
    cudaGetSymbolAddress((void**)&W1t,    g_W1t);
    cudaGetSymbolAddress((void**)&W2t,    g_W2t);

    const int LIN_SMEM = (int)(Core<128, 2, 4>::STG * 2 * sizeof(uint32_t)); // 67584
    const int AV_SMEM  = (int)(Core<64, 4, 2>::STG * 2 * sizeof(uint32_t));  // 51200
    cudaFuncSetAttribute(linear_bf<false, false, false>, cudaFuncAttributeMaxDynamicSharedMemorySize, LIN_SMEM);
    cudaFuncSetAttribute(linear_bf<true, true, false>,   cudaFuncAttributeMaxDynamicSharedMemorySize, LIN_SMEM);
    cudaFuncSetAttribute(linear_bf<true, false, true>,   cudaFuncAttributeMaxDynamicSharedMemorySize, LIN_SMEM);
    cudaFuncSetAttribute(score_bf, cudaFuncAttributeMaxDynamicSharedMemorySize, LIN_SMEM);
    cudaFuncSetAttribute(av_bf,    cudaFuncAttributeMaxDynamicSharedMemorySize, AV_SMEM);

    dim3 tb(32, 8);

    // 1. nX = LN(X)
    ln_kernel<<<NTOK, 256>>>(X, attn_g, attn_b, nullptr, nX);

    // 2. weight transposes -> K-major [N, K] layouts
    transpose_tiled<<<dim3(2, 32, 16), tb>>>(WQ, Wq, DMODEL, HP, 65536LL, 65536LL);
    transpose_tiled<<<dim3(2, 32, 16), tb>>>(WK, Wk, DMODEL, HP, 65536LL, 65536LL);
    transpose_tiled<<<dim3(2, 32, 16), tb>>>(WV, Wv, DMODEL, HP, 65536LL, 65536LL);
    transpose_tiled<<<dim3(32, 32, 1), tb>>>(WO, Wot, DMODEL, DMODEL, 0LL, 0LL);
    transpose_tiled<<<dim3(FFDIM / 32, 32, 1), tb>>>(fW1, W1t, DMODEL, FFDIM, 0LL, 0LL);
    transpose_tiled<<<dim3(32, FFDIM / 32, 1), tb>>>(fW2, W2t, FFDIM, DMODEL, 0LL, 0LL);

    // 3. Q/K/V projections (bf16x2 mma)
    dim3 gQKV(DMODEL / 128, NTOK / 128);
    linear_bf<false, false, false><<<gQKV, 256, LIN_SMEM>>>(nX, Wq, nullptr, nullptr, Q, DMODEL, DMODEL);
    linear_bf<false, false, false><<<gQKV, 256, LIN_SMEM>>>(nX, Wk, nullptr, nullptr, K, DMODEL, DMODEL);
    linear_bf<false, false, false><<<gQKV, 256, LIN_SMEM>>>(nX, Wv, nullptr, nullptr, V, DMODEL, DMODEL);

    // 4. V transpose for AV
    vt_kernel<<<dim3(TLEN / 32, HP / 32, BATCH * NH), tb>>>(V, Vt);

    // 5. scores -> attn; 6. softmax in-place; 7. nv = attn @ V
    score_bf<<<dim3(TLEN / 128, TLEN / 128, BATCH * NH), 256, LIN_SMEM>>>(K, Q, attn);
    softmax_kernel<<<BATCH * NH * TLEN, 256>>>(attn);
    av_bf<<<dim3(TLEN / 128, 1, BATCH * NH), 256, AV_SMEM>>>(attn, Vt, nv);

    // 8. seq_summary = nv @ WO
    linear_bf<false, false, false><<<gQKV, 256, LIN_SMEM>>>(nv, Wot, nullptr, nullptr, ss, DMODEL, DMODEL);

    // 9. pre_ff = X + LN(ss)
    ln_kernel<<<NTOK, 256>>>(ss, ff_g, ff_b, X, preff);

    // 10. hidden = gelu(pre_ff @ fW1 + fb1)
    linear_bf<true, true, false><<<dim3(FFDIM / 128, NTOK / 128), 256, LIN_SMEM>>>(
        preff, W1t, fb1, nullptr, hidden, FFDIM, DMODEL);

    // 11. out = hidden @ fW2 + fb2 + pre_ff
    linear_bf<true, false, true><<<dim3(DMODEL / 128, NTOK / 128), 256, LIN_SMEM>>>(
        hidden, W2t, fb2, preff, out, DMODEL, FFDIM);
}

// round 12
// speedup vs baseline: 2.0793x; 1.0003x over previous
#include <cuda_runtime.h>
#include <cstdint>
#include <math.h>

#define BATCH 4
#define TLEN 2048
#define DMODEL 1024
#define NH 16
#define HP 64
#define FFDIM 4096
#define NTOK (BATCH * TLEN)   // 8192

// ---------------- scratch (static __device__, allocation-free) ----------------
__device__ float g_nX   [(size_t)NTOK * DMODEL];
__device__ float g_Q    [(size_t)NTOK * DMODEL];
__device__ float g_Kb   [(size_t)NTOK * DMODEL];
__device__ float g_V    [(size_t)NTOK * DMODEL];
__device__ float g_Vt   [(size_t)NTOK * DMODEL];      // [b,h,p,t]
__device__ float g_nv   [(size_t)NTOK * DMODEL];
__device__ float g_ss   [(size_t)NTOK * DMODEL];
__device__ float g_preff[(size_t)NTOK * DMODEL];
__device__ float g_hidden[(size_t)NTOK * FFDIM];
__device__ float g_Wq [DMODEL * DMODEL];               // [h*P+p, d]  (K-major)
__device__ float g_Wk [DMODEL * DMODEL];
__device__ float g_Wv [DMODEL * DMODEL];
__device__ float g_Wot[DMODEL * DMODEL];               // [d, h*P+p]
__device__ float g_W1t[(size_t)DMODEL * FFDIM];        // [ff, d]
__device__ float g_W2t[(size_t)DMODEL * FFDIM];        // [d, ff]

// ---------------- helpers ----------------
__device__ __forceinline__ uint32_t packbf(float lo, float hi) {
    // low 16 bits = bf16(lo), high 16 = bf16(hi)
    uint32_t u;
    asm("cvt.rn.bf16x2.f32 %0, %1, %2;" : "=r"(u) : "f"(hi), "f"(lo));
    return u;
}
__device__ __forceinline__ float lo_f(uint32_t u) { return __uint_as_float(u << 16); }
__device__ __forceinline__ float hi_f(uint32_t u) { return __uint_as_float(u & 0xFFFF0000u); }

#define MMA_BF16(d, a, b)                                                     \
    asm volatile(                                                             \
        "mma.sync.aligned.m16n8k16.row.col.f32.bf16.bf16.f32 "               \
        "{%0,%1,%2,%3}, {%4,%5,%6,%7}, {%8,%9}, {%0,%1,%2,%3};"               \
        : "+f"(d[0]), "+f"(d[1]), "+f"(d[2]), "+f"(d[3])                      \
        : "r"(a[0]), "r"(a[1]), "r"(a[2]), "r"(a[3]), "r"(b[0]), "r"(b[1]))

__device__ __forceinline__ float gelu_f(float v) {
    return 0.5f * v * (1.0f + erff(v * 0.70710678118654752f));
}

// ---------------- bf16x2-split mma core ----------------
// BM=128, BK=32 (16 k-pairs). A: [128,K] row-major; B: [BN,K] row-major (K-major).
// SMEM planes per stage (uint32): Ah[16][132], Al, Bh[16][BN+4], Bl.
// Double-buffered: gmem prefetch -> regs, convert+store after mma, 1 sync/tile.
template<int BN, int WARPS_M, int WARPS_N>
struct Core {
    static constexpr int BM = 128, KP = 16;       // k-pairs per tile (BK=32)
    static constexpr int WM = BM / WARPS_M, WN = BN / WARPS_N;
    static constexpr int MT = WM / 16, NT = WN / 8;
    static constexpr int AP = BM + 4, BP = BN + 4;
    static constexpr int ASZ = KP * AP, BSZ = KP * BP;
    static constexpr int STG = 2 * ASZ + 2 * BSZ; // uint32 per stage
    static constexpr int NA = 4, NB = BN / 32;    // float4 loads per thread

    __device__ static __forceinline__ void cvt_store(
        uint32_t* __restrict__ H, uint32_t* __restrict__ L,
        int c, int r, int P, float4 v)
    {
        uint32_t h01 = packbf(v.x, v.y);
        uint32_t h23 = packbf(v.z, v.w);
        float r0 = v.x - lo_f(h01), r1 = v.y - hi_f(h01);
        float r2 = v.z - lo_f(h23), r3 = v.w - hi_f(h23);
        H[(2 * c)     * P + r] = h01;
        H[(2 * c + 1) * P + r] = h23;
        L[(2 * c)     * P + r] = packbf(r0, r1);
        L[(2 * c + 1) * P + r] = packbf(r2, r3);
    }

    __device__ static __forceinline__ void stage_to(
        uint32_t* st, const float4* pa, const float4* pb, int t)
    {
        uint32_t* Ah = st;
        uint32_t* Al = st + ASZ;
        uint32_t* Bh = Al + ASZ;
        uint32_t* Bl = Bh + BSZ;
        #pragma unroll
        for (int i = 0; i < NA; i++) {
            int f = t + i * 256;
            cvt_store(Ah, Al, f & 7, f >> 3, AP, pa[i]);
        }
        #pragma unroll
        for (int i = 0; i < NB; i++) {
            int f = t + i * 256;
            cvt_store(Bh, Bl, f & 7, f >> 3, BP, pb[i]);
        }
    }

    __device__ static __forceinline__ void run(
        const float* __restrict__ Ag, int lda,
        const float* __restrict__ Bg, int ldb, int K,
        uint32_t* sm, float (&acc)[MT][NT][4])
    {
        const int t = threadIdx.x, lane = t & 31, wid = t >> 5;
        const int g = lane >> 2, tg = lane & 3;
        const int warpM = wid / WARPS_N, warpN = wid % WARPS_N;

        #pragma unroll
        for (int mt = 0; mt < MT; mt++)
            #pragma unroll
            for (int nt = 0; nt < NT; nt++)
                #pragma unroll
                for (int i = 0; i < 4; i++) acc[mt][nt][i] = 0.f;

        const int KT = K >> 5;
        float4 pa[NA], pb[NB];

        // preload tile 0
        #pragma unroll
        for (int i = 0; i < NA; i++) {
            int f = t + i * 256;
            pa[i] = *(const float4*)(Ag + (size_t)(f >> 3) * lda + (f & 7) * 4);
        }
        #pragma unroll
        for (int i = 0; i < NB; i++) {
            int f = t + i * 256;
            pb[i] = *(const float4*)(Bg + (size_t)(f >> 3) * ldb + (f & 7) * 4);
        }
        stage_to(sm, pa, pb, t);
        __syncthreads();

        for (int kt = 0; kt < KT; kt++) {
            int s = kt & 1;
            if (kt + 1 < KT) {
                int k0 = (kt + 1) << 5;
                #pragma unroll
                for (int i = 0; i < NA; i++) {
                    int f = t + i * 256;
                    pa[i] = *(const float4*)(Ag + (size_t)(f >> 3) * lda + k0 + (f & 7) * 4);
                }
                #pragma unroll
                for (int i = 0; i < NB; i++) {
                    int f = t + i * 256;
                    pb[i] = *(const float4*)(Bg + (size_t)(f >> 3) * ldb + k0 + (f & 7) * 4);
                }
            }
            uint32_t* Ah = sm + s * STG;
            uint32_t* Al = Ah + ASZ;
            uint32_t* Bh = Al + ASZ;
            uint32_t* Bl = Bh + BSZ;
            #pragma unroll
            for (int ks = 0; ks < 2; ks++) {
                int kb = ks * 8;
                uint32_t ahi[MT][4], alo[MT][4], bhi[NT][2], blo[NT][2];
                #pragma unroll
                for (int mt = 0; mt < MT; mt++) {
                    int m = warpM * WM + mt * 16 + g;
                    int i0 = (kb + tg) * AP + m;
                    int i1 = (kb + tg + 4) * AP + m;
                    ahi[mt][0] = Ah[i0]; ahi[mt][1] = Ah[i0 + 8];
                    ahi[mt][2] = Ah[i1]; ahi[mt][3] = Ah[i1 + 8];
                    alo[mt][0] = Al[i0]; alo[mt][1] = Al[i0 + 8];
                    alo[mt][2] = Al[i1]; alo[mt][3] = Al[i1 + 8];
                }
                #pragma unroll
                for (int nt = 0; nt < NT; nt++) {
                    int n = warpN * WN + nt * 8 + g;
                    int j0 = (kb + tg) * BP + n;
                    int j1 = (kb + tg + 4) * BP + n;
                    bhi[nt][0] = Bh[j0]; bhi[nt][1] = Bh[j1];
                    blo[nt][0] = Bl[j0]; blo[nt][1] = Bl[j1];
                }
                #pragma unroll
                for (int mt = 0; mt < MT; mt++)
                    #pragma unroll
                    for (int nt = 0; nt < NT; nt++) MMA_BF16(acc[mt][nt], ahi[mt], bhi[nt]);
                #pragma unroll
                for (int mt = 0; mt < MT; mt++)
                    #pragma unroll
                    for (int nt = 0; nt < NT; nt++) MMA_BF16(acc[mt][nt], ahi[mt], blo[nt]);
                #pragma unroll
                for (int mt = 0; mt < MT; mt++)
                    #pragma unroll
                    for (int nt = 0; nt < NT; nt++) MMA_BF16(acc[mt][nt], alo[mt], bhi[nt]);
            }
            if (kt + 1 < KT) stage_to(sm + (s ^ 1) * STG, pa, pb, t);
            __syncthreads();
        }
    }
};

// ---------------- linear: C[M,N] = A[M,K] @ Bt[N,K]^T (+bias/gelu/resid) ----------------
template<bool BIAS, bool GELU, bool RESID>
__global__ void __launch_bounds__(256, 1) linear_bf(
    const float* __restrict__ A, const float* __restrict__ Bt,
    const float* __restrict__ bias, const float* __restrict__ resid,
    float* __restrict__ C, int N, int K)
{
    using Co = Core<128, 2, 4>;
    extern __shared__ uint32_t sm[];
    float acc[Co::MT][Co::NT][4];
    Co::run(A + (size_t)blockIdx.y * 128 * K, K,
            Bt + (size_t)blockIdx.x * 128 * K, K, K, sm, acc);

    int t = threadIdx.x, lane = t & 31, wid = t >> 5;
    int g = lane >> 2, tg = lane & 3;
    int warpM = wid / 4, warpN = wid % 4;
    int row0 = blockIdx.y * 128 + warpM * Co::WM;
    int col0 = blockIdx.x * 128 + warpN * Co::WN;
    #pragma unroll
    for (int mt = 0; mt < Co::MT; mt++) {
        int row = row0 + mt * 16 + g;
        #pragma unroll
        for (int nt = 0; nt < Co::NT; nt++) {
            int col = col0 + nt * 8 + tg * 2;
            float v0 = acc[mt][nt][0], v1 = acc[mt][nt][1];
            float v2 = acc[mt][nt][2], v3 = acc[mt][nt][3];
            if (BIAS) {
                float b0 = bias[col], b1 = bias[col + 1];
                v0 += b0; v1 += b1; v2 += b0; v3 += b1;
            }
            if (GELU) { v0 = gelu_f(v0); v1 = gelu_f(v1); v2 = gelu_f(v2); v3 = gelu_f(v3); }
            if (RESID) {
                float2 r0 = *(const float2*)(resid + (size_t)row * N + col);
                float2 r1 = *(const float2*)(resid + (size_t)(row + 8) * N + col);
                v0 += r0.x; v1 += r0.y; v2 += r1.x; v3 += r1.y;
            }
            *(float2*)(C + (size_t)row * N + col) = make_float2(v0, v1);
            *(float2*)(C + (size_t)(row + 8) * N + col) = make_float2(v2, v3);
        }
    }
}

// ---------------- scores: S[q,k] = (K_q . Q_k)/8 per (b,h) ----------------
__global__ void __launch_bounds__(256, 1) score_bf(
    const float* __restrict__ Kbuf, const float* __restrict__ Qbuf,
    float* __restrict__ S)
{
    using Co = Core<128, 2, 4>;
    extern __shared__ uint32_t sm[];
    int bh = blockIdx.z, b = bh >> 4, h = bh & 15;
    float acc[Co::MT][Co::NT][4];
    Co::run(Kbuf + (size_t)b * TLEN * DMODEL + h * HP + (size_t)blockIdx.y * 128 * DMODEL, DMODEL,
            Qbuf + (size_t)b * TLEN * DMODEL + h * HP + (size_t)blockIdx.x * 128 * DMODEL, DMODEL,
            HP, sm, acc);

    int t = threadIdx.x, lane = t & 31, wid = t >> 5;
    int g = lane >> 2, tg = lane & 3;
    int warpM = wid / 4, warpN = wid % 4;
    float* Sb = S + (size_t)bh * TLEN * TLEN;
    int row0 = blockIdx.y * 128 + warpM * Co::WM;
    int col0 = blockIdx.x * 128 + warpN * Co::WN;
    #pragma unroll
    for (int mt = 0; mt < Co::MT; mt++) {
        int row = row0 + mt * 16 + g;
        #pragma unroll
        for (int nt = 0; nt < Co::NT; nt++) {
            int col = col0 + nt * 8 + tg * 2;
            *(float2*)(Sb + (size_t)row * TLEN + col) =
                make_float2(acc[mt][nt][0] * 0.125f, acc[mt][nt][1] * 0.125f);
            *(float2*)(Sb + (size_t)(row + 8) * TLEN + col) =
                make_float2(acc[mt][nt][2] * 0.125f, acc[mt][nt][3] * 0.125f);
        }
    }
}

// ---------------- AV: nv[q,p] = sum_t attn[q,t] Vt[p,t] per (b,h) ----------------
__global__ void __launch_bounds__(256, 1) av_bf(
    const float* __restrict__ Attn, const float* __restrict__ Vt,
    float* __restrict__ O)
{
    using Co = Core<64, 4, 2>;
    extern __shared__ uint32_t sm[];
    int bh = blockIdx.z, b = bh >> 4, h = bh & 15;
    float acc[Co::MT][Co::NT][4];
    Co::run(Attn + (size_t)bh * TLEN * TLEN + (size_t)blockIdx.x * 128 * TLEN, TLEN,
            Vt + (size_t)bh * HP * TLEN, TLEN, TLEN, sm, acc);

    int t = threadIdx.x, lane = t & 31, wid = t >> 5;
    int g = lane >> 2, tg = lane & 3;
    int warpM = wid / 2, warpN = wid % 2;
    #pragma unroll
    for (int mt = 0; mt < Co::MT; mt++) {
        int row = warpM * Co::WM + mt * 16 + g;
        float* Crow = O + ((size_t)b * TLEN + blockIdx.x * 128 + row) * DMODEL + h * HP;
        #pragma unroll
        for (int nt = 0; nt < Co::NT; nt++) {
            int col = warpN * Co::WN + nt * 8 + tg * 2;
            *(float2*)(Crow + col) = make_float2(acc[mt][nt][0], acc[mt][nt][1]);
            *(float2*)(Crow + 8 * DMODEL + col) = make_float2(acc[mt][nt][2], acc[mt][nt][3]);
        }
    }
}

// ---------------- tiled transpose: out[C,R] = in[R,C]^T, batched ----------------
__global__ void transpose_tiled(const float* __restrict__ in, float* __restrict__ out,
                                int R, int C, long long inBS, long long outBS)
{
    __shared__ float tile[32][33];
    const float* I = in + (size_t)blockIdx.z * inBS;
    float* Ot = out + (size_t)blockIdx.z * outBS;
    int c0 = blockIdx.x * 32, r0 = blockIdx.y * 32;
    int tx = threadIdx.x, ty = threadIdx.y;
    #pragma unroll
    for (int j = 0; j < 32; j += 8)
        tile[ty + j][tx] = I[(size_t)(r0 + ty + j) * C + c0 + tx];
    __syncthreads();
    #pragma unroll
    for (int j = 0; j < 32; j += 8)
        Ot[(size_t)(c0 + ty + j) * R + r0 + tx] = tile[tx][ty + j];
}

// ---------------- V transpose: Vt[b,h,p,t] = V[b,t,h*64+p] ----------------
__global__ void vt_kernel(const float* __restrict__ V, float* __restrict__ Vt)
{
    __shared__ float tile[32][33];
    int bh = blockIdx.z, b = bh >> 4, h = bh & 15;
    int t0 = blockIdx.x * 32, p0 = blockIdx.y * 32;
    int tx = threadIdx.x, ty = threadIdx.y;
    const float* I = V + (size_t)b * TLEN * DMODEL + h * HP;
    #pragma unroll
    for (int j = 0; j < 32; j += 8)
        tile[ty + j][tx] = I[(size_t)(t0 + ty + j) * DMODEL + p0 + tx];
    __syncthreads();
    float* O = Vt + (size_t)bh * HP * TLEN;
    #pragma unroll
    for (int j = 0; j < 32; j += 8)
        O[(size_t)(p0 + ty + j) * TLEN + t0 + tx] = tile[tx][ty + j];
}

// ---------------- LayerNorm (one block per row of 1024) ----------------
__global__ void __launch_bounds__(256) ln_kernel(
    const float* __restrict__ x, const float* __restrict__ g,
    const float* __restrict__ b, const float* __restrict__ resid,
    float* __restrict__ out)
{
    int row = blockIdx.x;
    int t = threadIdx.x;
    const float4* xr = (const float4*)(x + (size_t)row * DMODEL);
    float4 v = xr[t];
    float s  = v.x + v.y + v.z + v.w;
    float s2 = v.x*v.x + v.y*v.y + v.z*v.z + v.w*v.w;
    #pragma unroll
    for (int o = 16; o > 0; o >>= 1) {
        s  += __shfl_xor_sync(0xffffffffu, s,  o);
        s2 += __shfl_xor_sync(0xffffffffu, s2, o);
    }
    __shared__ float shs[8], shs2[8];
    __shared__ float mean_s, rstd_s;
    int wid = t >> 5, lane = t & 31;
    if (lane == 0) { shs[wid] = s; shs2[wid] = s2; }
    __syncthreads();
    if (t == 0) {
        float ts = 0.f, ts2 = 0.f;
        #pragma unroll
        for (int i = 0; i < 8; i++) { ts += shs[i]; ts2 += shs2[i]; }
        float mean = ts * (1.0f / DMODEL);
        float var  = ts2 * (1.0f / DMODEL) - mean * mean;
        mean_s = mean;
        rstd_s = rsqrtf(var + 1e-5f);
    }
    __syncthreads();
    float m = mean_s, r = rstd_s;
    float4 gv = ((const float4*)g)[t];
    float4 bv = ((const float4*)b)[t];
    float4 o;
    o.x = (v.x - m) * r * gv.x + bv.x;
    o.y = (v.y - m) * r * gv.y + bv.y;
    o.z = (v.z - m) * r * gv.z + bv.z;
    o.w = (v.w - m) * r * gv.w + bv.w;
    if (resid) {
        float4 rv = ((const float4*)(resid + (size_t)row * DMODEL))[t];
        o.x += rv.x; o.y += rv.y; o.z += rv.z; o.w += rv.w;
    }
    ((float4*)(out + (size_t)row * DMODEL))[t] = o;
}

// ---------------- row softmax over 2048 (in-place) ----------------
__global__ void __launch_bounds__(256) softmax_kernel(float* __restrict__ S)
{
    size_t row = blockIdx.x;
    float* r = S + row * (size_t)TLEN;
    int t = threadIdx.x;
    float4 v0 = ((float4*)r)[t];
    float4 v1 = ((float4*)r)[t + 256];
    float mx = fmaxf(fmaxf(fmaxf(v0.x, v0.y), fmaxf(v0.z, v0.w)),
                     fmaxf(fmaxf(v1.x, v1.y), fmaxf(v1.z, v1.w)));
    #pragma unroll
    for (int o = 16; o > 0; o >>= 1) mx = fmaxf(mx, __shfl_xor_sync(0xffffffffu, mx, o));
    __shared__ float sm[8];
    __shared__ float mx_s, inv_s;
    int wid = t >> 5, lane = t & 31;
    if (lane == 0) sm[wid] = mx;
    __syncthreads();
    if (t == 0) {
        float m = sm[0];
        #pragma unroll
        for (int i = 1; i < 8; i++) m = fmaxf(m, sm[i]);
        mx_s = m;
    }
    __syncthreads();
    float m = mx_s;
    v0.x = __expf(v0.x - m); v0.y = __expf(v0.y - m);
    v0.z = __expf(v0.z - m); v0.w = __expf(v0.w - m);
    v1.x = __expf(v1.x - m); v1.y = __expf(v1.y - m);
    v1.z = __expf(v1.z - m); v1.w = __expf(v1.w - m);
    float s = v0.x + v0.y + v0.z + v0.w + v1.x + v1.y + v1.z + v1.w;
    #pragma unroll
    for (int o = 16; o > 0; o >>= 1) s += __shfl_xor_sync(0xffffffffu, s, o);
    if (lane == 0) sm[wid] = s;
    __syncthreads();
    if (t == 0) {
        float ts = 0.f;
        #pragma unroll
        for (int i = 0; i < 8; i++) ts += sm[i];
        inv_s = 1.0f / ts;
    }
    __syncthreads();
    float inv = inv_s;
    v0.x *= inv; v0.y *= inv; v0.z *= inv; v0.w *= inv;
    v1.x *= inv; v1.y *= inv; v1.z *= inv; v1.w *= inv;
    ((float4*)r)[t] = v0;
    ((float4*)r)[t + 256] = v1;
}

// ---------------- launch ----------------
extern "C" void kernel_launch(void* const* d_in, const int* in_sizes, int n_in,
                              void* d_out, int out_size)
{
    const float* X      = (const float*)d_in[0];
    const float* WQ     = (const float*)d_in[1];
    const float* WK     = (const float*)d_in[2];
    const float* WV     = (const float*)d_in[3];
    const float* WO     = (const float*)d_in[4];
    const float* attn_g = (const float*)d_in[5];
    const float* attn_b = (const float*)d_in[6];
    const float* ff_g   = (const float*)d_in[7];
    const float* ff_b   = (const float*)d_in[8];
    const float* fW1    = (const float*)d_in[9];
    const float* fb1    = (const float*)d_in[10];
    const float* fW2    = (const float*)d_in[11];
    const float* fb2    = (const float*)d_in[12];

    float* out  = (float*)d_out;
    float* attn = out + (size_t)NTOK * DMODEL;   // [B,H,T,T]

    float *nX, *Q, *K, *V, *Vt, *nv, *ss, *preff, *hidden;
    float *Wq, *Wk, *Wv, *Wot, *W1t, *W2t;
    cudaGetSymbolAddress((void**)&nX,     g_nX);
    cudaGetSymbolAddress((void**)&Q,      g_Q);
    cudaGetSymbolAddress((void**)&K,      g_Kb);
    cudaGetSymbolAddress((void**)&V,      g_V);
    cudaGetSymbolAddress((void**)&Vt,     g_Vt);
    cudaGetSymbolAddress((void**)&nv,     g_nv);
    cudaGetSymbolAddress((void**)&ss,     g_ss);
    cudaGetSymbolAddress((void**)&preff,  g_preff);
    cudaGetSymbolAddress((void**)&hidden, g_hidden);
    cudaGetSymbolAddress((void**)&Wq,     g_Wq);
    cudaGetSymbolAddress((void**)&Wk,     g_Wk);
    cudaGetSymbolAddress((void**)&Wv,     g_Wv);
    cudaGetSymbolAddress((void**)&Wot,    g_Wot);
    cudaGetSymbolAddress((void**)&W1t,    g_W1t);
    cudaGetSymbolAddress((void**)&W2t,    g_W2t);

    const int LIN_SMEM = (int)(Core<128, 2, 4>::STG * 2 * sizeof(uint32_t)); // 67584
    const int AV_SMEM  = (int)(Core<64, 4, 2>::STG * 2 * sizeof(uint32_t));  // 51200
    cudaFuncSetAttribute(linear_bf<false, false, false>, cudaFuncAttributeMaxDynamicSharedMemorySize, LIN_SMEM);
    cudaFuncSetAttribute(linear_bf<true, true, false>,   cudaFuncAttributeMaxDynamicSharedMemorySize, LIN_SMEM);
    cudaFuncSetAttribute(linear_bf<true, false, true>,   cudaFuncAttributeMaxDynamicSharedMemorySize, LIN_SMEM);
    cudaFuncSetAttribute(score_bf, cudaFuncAttributeMaxDynamicSharedMemorySize, LIN_SMEM);
    cudaFuncSetAttribute(av_bf,    cudaFuncAttributeMaxDynamicSharedMemorySize, AV_SMEM);

    dim3 tb(32, 8);

    // 1. nX = LN(X)
    ln_kernel<<<NTOK, 256>>>(X, attn_g, attn_b, nullptr, nX);

    // 2. weight transposes -> K-major [N, K] layouts
    transpose_tiled<<<dim3(2, 32, 16), tb>>>(WQ, Wq, DMODEL, HP, 65536LL, 65536LL);
    transpose_tiled<<<dim3(2, 32, 16), tb>>>(WK, Wk, DMODEL, HP, 65536LL, 65536LL);
    transpose_tiled<<<dim3(2, 32, 16), tb>>>(WV, Wv, DMODEL, HP, 65536LL, 65536LL);
    transpose_tiled<<<dim3(32, 32, 1), tb>>>(WO, Wot, DMODEL, DMODEL, 0LL, 0LL);
    transpose_tiled<<<dim3(FFDIM / 32, 32, 1), tb>>>(fW1, W1t, DMODEL, FFDIM, 0LL, 0LL);
    transpose_tiled<<<dim3(32, FFDIM / 32, 1), tb>>>(fW2, W2t, FFDIM, DMODEL, 0LL, 0LL);

    // 3. Q/K/V projections (bf16x2 mma)
    dim3 gQKV(DMODEL / 128, NTOK / 128);
    linear_bf<false, false, false><<<gQKV, 256, LIN_SMEM>>>(nX, Wq, nullptr, nullptr, Q, DMODEL, DMODEL);
    linear_bf<false, false, false><<<gQKV, 256, LIN_SMEM>>>(nX, Wk, nullptr, nullptr, K, DMODEL, DMODEL);
    linear_bf<false, false, false><<<gQKV, 256, LIN_SMEM>>>(nX, Wv, nullptr, nullptr, V, DMODEL, DMODEL);

    // 4. V transpose for AV
    vt_kernel<<<dim3(TLEN / 32, HP / 32, BATCH * NH), tb>>>(V, Vt);

    // 5. scores -> attn; 6. softmax in-place; 7. nv = attn @ V
    score_bf<<<dim3(TLEN / 128, TLEN / 128, BATCH * NH), 256, LIN_SMEM>>>(K, Q, attn);
    softmax_kernel<<<BATCH * NH * TLEN, 256>>>(attn);
    av_bf<<<dim3(TLEN / 128, 1, BATCH * NH), 256, AV_SMEM>>>(attn, Vt, nv);

    // 8. seq_summary = nv @ WO
    linear_bf<false, false, false><<<gQKV, 256, LIN_SMEM>>>(nv, Wot, nullptr, nullptr, ss, DMODEL, DMODEL);

    // 9. pre_ff = X + LN(ss)
    ln_kernel<<<NTOK, 256>>>(ss, ff_g, ff_b, X, preff);

    // 10. hidden = gelu(pre_ff @ fW1 + fb1)
    linear_bf<true, true, false><<<dim3(FFDIM / 128, NTOK / 128), 256, LIN_SMEM>>>(
        preff, W1t, fb1, nullptr, hidden, FFDIM, DMODEL);

    // 11. out = hidden @ fW2 + fb2 + pre_ff
    linear_bf<true, false, true><<<dim3(DMODEL / 128, NTOK / 128), 256, LIN_SMEM>>>(
        hidden, W2t, fb2, preff, out, DMODEL, FFDIM);
}

// round 13
// speedup vs baseline: 2.0829x; 1.0017x over previous
#include <cuda_runtime.h>
#include <cstdint>
#include <math.h>

#define BATCH 4
#define TLEN 2048
#define DMODEL 1024
#define NH 16
#define HP 64
#define FFDIM 4096
#define NTOK (BATCH * TLEN)   // 8192

// ---------------- scratch (static __device__, allocation-free) ----------------
__device__ float g_nX   [(size_t)NTOK * DMODEL];
__device__ float g_Q    [(size_t)NTOK * DMODEL];
__device__ float g_Kb   [(size_t)NTOK * DMODEL];
__device__ float g_V    [(size_t)NTOK * DMODEL];
__device__ float g_Vt   [(size_t)NTOK * DMODEL];      // [b,h,p,t]
__device__ float g_nv   [(size_t)NTOK * DMODEL];
__device__ float g_ss   [(size_t)NTOK * DMODEL];
__device__ float g_preff[(size_t)NTOK * DMODEL];
__device__ float g_hidden[(size_t)NTOK * FFDIM];
__device__ float g_Wq [DMODEL * DMODEL];               // [h*P+p, d]  (K-major)
__device__ float g_Wk [DMODEL * DMODEL];
__device__ float g_Wv [DMODEL * DMODEL];
__device__ float g_Wot[DMODEL * DMODEL];               // [d, h*P+p]
__device__ float g_W1t[(size_t)DMODEL * FFDIM];        // [ff, d]
__device__ float g_W2t[(size_t)DMODEL * FFDIM];        // [d, ff]

// ---------------- helpers ----------------
__device__ __forceinline__ uint32_t packbf(float lo, float hi) {
    // low 16 bits = bf16(lo), high 16 = bf16(hi)
    uint32_t u;
    asm("cvt.rn.bf16x2.f32 %0, %1, %2;" : "=r"(u) : "f"(hi), "f"(lo));
    return u;
}
__device__ __forceinline__ float lo_f(uint32_t u) { return __uint_as_float(u << 16); }
__device__ __forceinline__ float hi_f(uint32_t u) { return __uint_as_float(u & 0xFFFF0000u); }

#define MMA_BF16(d, a, b)                                                     \
    asm volatile(                                                             \
        "mma.sync.aligned.m16n8k16.row.col.f32.bf16.bf16.f32 "               \
        "{%0,%1,%2,%3}, {%4,%5,%6,%7}, {%8,%9}, {%0,%1,%2,%3};"               \
        : "+f"(d[0]), "+f"(d[1]), "+f"(d[2]), "+f"(d[3])                      \
        : "r"(a[0]), "r"(a[1]), "r"(a[2]), "r"(a[3]), "r"(b[0]), "r"(b[1]))

__device__ __forceinline__ float gelu_f(float v) {
    return 0.5f * v * (1.0f + erff(v * 0.70710678118654752f));
}

// ---------------- bf16x2-split mma core ----------------
// BM=128, BK=32 (16 k-pairs). A: [128,K] row-major; B: [BN,K] row-major (K-major).
// SMEM planes per stage (uint32): Ah[16][132], Al, Bh[16][BN+4], Bl.
// Double-buffered: gmem prefetch -> regs, convert+store after mma, 1 sync/tile.
template<int BN, int WARPS_M, int WARPS_N>
struct Core {
    static constexpr int BM = 128, KP = 16;       // k-pairs per tile (BK=32)
    static constexpr int WM = BM / WARPS_M, WN = BN / WARPS_N;
    static constexpr int MT = WM / 16, NT = WN / 8;
    static constexpr int AP = BM + 4, BP = BN + 4;
    static constexpr int ASZ = KP * AP, BSZ = KP * BP;
    static constexpr int STG = 2 * ASZ + 2 * BSZ; // uint32 per stage
    static constexpr int NA = 4, NB = BN / 32;    // float4 loads per thread

    __device__ static __forceinline__ void cvt_store(
        uint32_t* __restrict__ H, uint32_t* __restrict__ L,
        int c, int r, int P, float4 v)
    {
        uint32_t h01 = packbf(v.x, v.y);
        uint32_t h23 = packbf(v.z, v.w);
        float r0 = v.x - lo_f(h01), r1 = v.y - hi_f(h01);
        float r2 = v.z - lo_f(h23), r3 = v.w - hi_f(h23);
        H[(2 * c)     * P + r] = h01;
        H[(2 * c + 1) * P + r] = h23;
        L[(2 * c)     * P + r] = packbf(r0, r1);
        L[(2 * c + 1) * P + r] = packbf(r2, r3);
    }

    __device__ static __forceinline__ void stage_to(
        uint32_t* st, const float4* pa, const float4* pb, int t)
    {
        uint32_t* Ah = st;
        uint32_t* Al = st + ASZ;
        uint32_t* Bh = Al + ASZ;
        uint32_t* Bl = Bh + BSZ;
        #pragma unroll
        for (int i = 0; i < NA; i++) {
            int f = t + i * 256;
            cvt_store(Ah, Al, f & 7, f >> 3, AP, pa[i]);
        }
        #pragma unroll
        for (int i = 0; i < NB; i++) {
            int f = t + i * 256;
            cvt_store(Bh, Bl, f & 7, f >> 3, BP, pb[i]);
        }
    }

    __device__ static __forceinline__ void run(
        const float* __restrict__ Ag, int lda,
        const float* __restrict__ Bg, int ldb, int K,
        uint32_t* sm, float (&acc)[MT][NT][4])
    {
        const int t = threadIdx.x, lane = t & 31, wid = t >> 5;
        const int g = lane >> 2, tg = lane & 3;
        const int warpM = wid / WARPS_N, warpN = wid % WARPS_N;

        #pragma unroll
        for (int mt = 0; mt < MT; mt++)
            #pragma unroll
            for (int nt = 0; nt < NT; nt++)
                #pragma unroll
                for (int i = 0; i < 4; i++) acc[mt][nt][i] = 0.f;

        const int KT = K >> 5;
        float4 pa[NA], pb[NB];

        // preload tile 0
        #pragma unroll
        for (int i = 0; i < NA; i++) {
            int f = t + i * 256;
            pa[i] = *(const float4*)(Ag + (size_t)(f >> 3) * lda + (f & 7) * 4);
        }
        #pragma unroll
        for (int i = 0; i < NB; i++) {
            int f = t + i * 256;
            pb[i] = *(const float4*)(Bg + (size_t)(f >> 3) * ldb + (f & 7) * 4);
        }
        stage_to(sm, pa, pb, t);
        __syncthreads();

        for (int kt = 0; kt < KT; kt++) {
            int s = kt & 1;
            if (kt + 1 < KT) {
                int k0 = (kt + 1) << 5;
                #pragma unroll
                for (int i = 0; i < NA; i++) {
                    int f = t + i * 256;
                    pa[i] = *(const float4*)(Ag + (size_t)(f >> 3) * lda + k0 + (f & 7) * 4);
                }
                #pragma unroll
                for (int i = 0; i < NB; i++) {
                    int f = t + i * 256;
                    pb[i] = *(const float4*)(Bg + (size_t)(f >> 3) * ldb + k0 + (f & 7) * 4);
                }
            }
            uint32_t* Ah = sm + s * STG;
            uint32_t* Al = Ah + ASZ;
            uint32_t* Bh = Al + ASZ;
            uint32_t* Bl = Bh + BSZ;
            #pragma unroll
            for (int ks = 0; ks < 2; ks++) {
                int kb = ks * 8;
                uint32_t ahi[MT][4], alo[MT][4], bhi[NT][2], blo[NT][2];
                #pragma unroll
                for (int mt = 0; mt < MT; mt++) {
                    int m = warpM * WM + mt * 16 + g;
                    int i0 = (kb + tg) * AP + m;
                    int i1 = (kb + tg + 4) * AP + m;
                    ahi[mt][0] = Ah[i0]; ahi[mt][1] = Ah[i0 + 8];
                    ahi[mt][2] = Ah[i1]; ahi[mt][3] = Ah[i1 + 8];
                    alo[mt][0] = Al[i0]; alo[mt][1] = Al[i0 + 8];
                    alo[mt][2] = Al[i1]; alo[mt][3] = Al[i1 + 8];
                }
                #pragma unroll
                for (int nt = 0; nt < NT; nt++) {
                    int n = warpN * WN + nt * 8 + g;
                    int j0 = (kb + tg) * BP + n;
                    int j1 = (kb + tg + 4) * BP + n;
                    bhi[nt][0] = Bh[j0]; bhi[nt][1] = Bh[j1];
                    blo[nt][0] = Bl[j0]; blo[nt][1] = Bl[j1];
                }
                #pragma unroll
                for (int mt = 0; mt < MT; mt++)
                    #pragma unroll
                    for (int nt = 0; nt < NT; nt++) MMA_BF16(acc[mt][nt], ahi[mt], bhi[nt]);
                #pragma unroll
                for (int mt = 0; mt < MT; mt++)
                    #pragma unroll
                    for (int nt = 0; nt < NT; nt++) MMA_BF16(acc[mt][nt], ahi[mt], blo[nt]);
                #pragma unroll
                for (int mt = 0; mt < MT; mt++)
                    #pragma unroll
                    for (int nt = 0; nt < NT; nt++) MMA_BF16(acc[mt][nt], alo[mt], bhi[nt]);
            }
            if (kt + 1 < KT) stage_to(sm + (s ^ 1) * STG, pa, pb, t);
            __syncthreads();
        }
    }
};

// ---------------- linear: C[M,N] = A[M,K] @ Bt[N,K]^T (+bias/gelu/resid) ----------------
template<bool BIAS, bool GELU, bool RESID>
__global__ void __launch_bounds__(256, 1) linear_bf(
    const float* __restrict__ A, const float* __restrict__ Bt,
    const float* __restrict__ bias, const float* __restrict__ resid,
    float* __restrict__ C, int N, int K)
{
    using Co = Core<128, 2, 4>;
    extern __shared__ uint32_t sm[];
    float acc[Co::MT][Co::NT][4];
    Co::run(A + (size_t)blockIdx.y * 128 * K, K,
            Bt + (size_t)blockIdx.x * 128 * K, K, K, sm, acc);

    int t = threadIdx.x, lane = t & 31, wid = t >> 5;
    int g = lane >> 2, tg = lane & 3;
    int warpM = wid / 4, warpN = wid % 4;
    int row0 = blockIdx.y * 128 + warpM * Co::WM;
    int col0 = blockIdx.x * 128 + warpN * Co::WN;
    #pragma unroll
    for (int mt = 0; mt < Co::MT; mt++) {
        int row = row0 + mt * 16 + g;
        #pragma unroll
        for (int nt = 0; nt < Co::NT; nt++) {
            int col = col0 + nt * 8 + tg * 2;
            float v0 = acc[mt][nt][0], v1 = acc[mt][nt][1];
            float v2 = acc[mt][nt][2], v3 = acc[mt][nt][3];
            if (BIAS) {
                float b0 = bias[col], b1 = bias[col + 1];
                v0 += b0; v1 += b1; v2 += b0; v3 += b1;
            }
            if (GELU) { v0 = gelu_f(v0); v1 = gelu_f(v1); v2 = gelu_f(v2); v3 = gelu_f(v3); }
            if (RESID) {
                float2 r0 = *(const float2*)(resid + (size_t)row * N + col);
                float2 r1 = *(const float2*)(resid + (size_t)(row + 8) * N + col);
                v0 += r0.x; v1 += r0.y; v2 += r1.x; v3 += r1.y;
            }
            *(float2*)(C + (size_t)row * N + col) = make_float2(v0, v1);
            *(float2*)(C + (size_t)(row + 8) * N + col) = make_float2(v2, v3);
        }
    }
}

// ---------------- scores: S[q,k] = (K_q . Q_k)/8 per (b,h) ----------------
__global__ void __launch_bounds__(256, 1) score_bf(
    const float* __restrict__ Kbuf, const float* __restrict__ Qbuf,
    float* __restrict__ S)
{
    using Co = Core<128, 2, 4>;
    extern __shared__ uint32_t sm[];
    int bh = blockIdx.z, b = bh >> 4, h = bh & 15;
    float acc[Co::MT][Co::NT][4];
    Co::run(Kbuf + (size_t)b * TLEN * DMODEL + h * HP + (size_t)blockIdx.y * 128 * DMODEL, DMODEL,
            Qbuf + (size_t)b * TLEN * DMODEL + h * HP + (size_t)blockIdx.x * 128 * DMODEL, DMODEL,
            HP, sm, acc);

    int t = threadIdx.x, lane = t & 31, wid = t >> 5;
    int g = lane >> 2, tg = lane & 3;
    int warpM = wid / 4, warpN = wid % 4;
    float* Sb = S + (size_t)bh * TLEN * TLEN;
    int row0 = blockIdx.y * 128 + warpM * Co::WM;
    int col0 = blockIdx.x * 128 + warpN * Co::WN;
    #pragma unroll
    for (int mt = 0; mt < Co::MT; mt++) {
        int row = row0 + mt * 16 + g;
        #pragma unroll
        for (int nt = 0; nt < Co::NT; nt++) {
            int col = col0 + nt * 8 + tg * 2;
            *(float2*)(Sb + (size_t)row * TLEN + col) =
                make_float2(acc[mt][nt][0] * 0.125f, acc[mt][nt][1] * 0.125f);
            *(float2*)(Sb + (size_t)(row + 8) * TLEN + col) =
                make_float2(acc[mt][nt][2] * 0.125f, acc[mt][nt][3] * 0.125f);
        }
    }
}

// ---------------- AV: nv[q,p] = sum_t attn[q,t] Vt[p,t] per (b,h) ----------------
__global__ void __launch_bounds__(256, 1) av_bf(
    const float* __restrict__ Attn, const float* __restrict__ Vt,
    float* __restrict__ O)
{
    using Co = Core<64, 4, 2>;
    extern __shared__ uint32_t sm[];
    int bh = blockIdx.z, b = bh >> 4, h = bh & 15;
    float acc[Co::MT][Co::NT][4];
    Co::run(Attn + (size_t)bh * TLEN * TLEN + (size_t)blockIdx.x * 128 * TLEN, TLEN,
            Vt + (size_t)bh * HP * TLEN, TLEN, TLEN, sm, acc);

    int t = threadIdx.x, lane = t & 31, wid = t >> 5;
    int g = lane >> 2, tg = lane & 3;
    int warpM = wid / 2, warpN = wid % 2;
    #pragma unroll
    for (int mt = 0; mt < Co::MT; mt++) {
        int row = warpM * Co::WM + mt * 16 + g;
        float* Crow = O + ((size_t)b * TLEN + blockIdx.x * 128 + row) * DMODEL + h * HP;
        #pragma unroll
        for (int nt = 0; nt < Co::NT; nt++) {
            int col = warpN * Co::WN + nt * 8 + tg * 2;
            *(float2*)(Crow + col) = make_float2(acc[mt][nt][0], acc[mt][nt][1]);
            *(float2*)(Crow + 8 * DMODEL + col) = make_float2(acc[mt][nt][2], acc[mt][nt][3]);
        }
    }
}

// ---------------- tiled transpose: out[C,R] = in[R,C]^T, batched ----------------
__global__ void transpose_tiled(const float* __restrict__ in, float* __restrict__ out,
                                int R, int C, long long inBS, long long outBS)
{
    __shared__ float tile[32][33];
    const float* I = in + (size_t)blockIdx.z * inBS;
    float* Ot = out + (size_t)blockIdx.z * outBS;
    int c0 = blockIdx.x * 32, r0 = blockIdx.y * 32;
    int tx = threadIdx.x, ty = threadIdx.y;
    #pragma unroll
    for (int j = 0; j < 32; j += 8)
        tile[ty + j][tx] = I[(size_t)(r0 + ty + j) * C + c0 + tx];
    __syncthreads();
    #pragma unroll
    for (int j = 0; j < 32; j += 8)
        Ot[(size_t)(c0 + ty + j) * R + r0 + tx] = tile[tx][ty + j];
}

// ---------------- V transpose: Vt[b,h,p,t] = V[b,t,h*64+p] ----------------
__global__ void vt_kernel(const float* __restrict__ V, float* __restrict__ Vt)
{
    __shared__ float tile[32][33];
    int bh = blockIdx.z, b = bh >> 4, h = bh & 15;
    int t0 = blockIdx.x * 32, p0 = blockIdx.y * 32;
    int tx = threadIdx.x, ty = threadIdx.y;
    const float* I = V + (size_t)b * TLEN * DMODEL + h * HP;
    #pragma unroll
    for (int j = 0; j < 32; j += 8)
        tile[ty + j][tx] = I[(size_t)(t0 + ty + j) * DMODEL + p0 + tx];
    __syncthreads();
    float* O = Vt + (size_t)bh * HP * TLEN;
    #pragma unroll
    for (int j = 0; j < 32; j += 8)
        O[(size_t)(p0 + ty + j) * TLEN + t0 + tx] = tile[tx][ty + j];
}

// ---------------- LayerNorm (one block per row of 1024) ----------------
__global__ void __launch_bounds__(256) ln_kernel(
    const float* __restrict__ x, const float* __restrict__ g,
    const float* __restrict__ b, const float* __restrict__ resid,
    float* __restrict__ out)
{
    int row = blockIdx.x;
    int t = threadIdx.x;
    const float4* xr = (const float4*)(x + (size_t)row * DMODEL);
    float4 v = xr[t];
    float s  = v.x + v.y + v.z + v.w;
    float s2 = v.x*v.x + v.y*v.y + v.z*v.z + v.w*v.w;
    #pragma unroll
    for (int o = 16; o > 0; o >>= 1) {
        s  += __shfl_xor_sync(0xffffffffu, s,  o);
        s2 += __shfl_xor_sync(0xffffffffu, s2, o);
    }
    __shared__ float shs[8], shs2[8];
    __shared__ float mean_s, rstd_s;
    int wid = t >> 5, lane = t & 31;
    if (lane == 0) { shs[wid] = s; shs2[wid] = s2; }
    __syncthreads();
    if (t == 0) {
        float ts = 0.f, ts2 = 0.f;
        #pragma unroll
        for (int i = 0; i < 8; i++) { ts += shs[i]; ts2 += shs2[i]; }
        float mean = ts * (1.0f / DMODEL);
        float var  = ts2 * (1.0f / DMODEL) - mean * mean;
        mean_s = mean;
        rstd_s = rsqrtf(var + 1e-5f);
    }
    __syncthreads();
    float m = mean_s, r = rstd_s;
    float4 gv = ((const float4*)g)[t];
    float4 bv = ((const float4*)b)[t];
    float4 o;
    o.x = (v.x - m) * r * gv.x + bv.x;
    o.y = (v.y - m) * r * gv.y + bv.y;
    o.z = (v.z - m) * r * gv.z + bv.z;
    o.w = (v.w - m) * r * gv.w + bv.w;
    if (resid) {
        float4 rv = ((const float4*)(resid + (size_t)row * DMODEL))[t];
        o.x += rv.x; o.y += rv.y; o.z += rv.z; o.w += rv.w;
    }
    ((float4*)(out + (size_t)row * DMODEL))[t] = o;
}

// ---------------- row softmax over 2048 (in-place) ----------------
__global__ void __launch_bounds__(256) softmax_kernel(float* __restrict__ S)
{
    size_t row = blockIdx.x;
    float* r = S + row * (size_t)TLEN;
    int t = threadIdx.x;
    float4 v0 = ((float4*)r)[t];
    float4 v1 = ((float4*)r)[t + 256];
    float mx = fmaxf(fmaxf(fmaxf(v0.x, v0.y), fmaxf(v0.z, v0.w)),
                     fmaxf(fmaxf(v1.x, v1.y), fmaxf(v1.z, v1.w)));
    #pragma unroll
    for (int o = 16; o > 0; o >>= 1) mx = fmaxf(mx, __shfl_xor_sync(0xffffffffu, mx, o));
    __shared__ float sm[8];
    __shared__ float mx_s, inv_s;
    int wid = t >> 5, lane = t & 31;
    if (lane == 0) sm[wid] = mx;
    __syncthreads();
    if (t == 0) {
        float m = sm[0];
        #pragma unroll
        for (int i = 1; i < 8; i++) m = fmaxf(m, sm[i]);
        mx_s = m;
    }
    __syncthreads();
    float m = mx_s;
    v0.x = __expf(v0.x - m); v0.y = __expf(v0.y - m);
    v0.z = __expf(v0.z - m); v0.w = __expf(v0.w - m);
    v1.x = __expf(v1.x - m); v1.y = __expf(v1.y - m);
    v1.z = __expf(v1.z - m); v1.w = __expf(v1.w - m);
    float s = v0.x + v0.y + v0.z + v0.w + v1.x + v1.y + v1.z + v1.w;
    #pragma unroll
    for (int o = 16; o > 0; o >>= 1) s += __shfl_xor_sync(0xffffffffu, s, o);
    if (lane == 0) sm[wid] = s;
    __syncthreads();
    if (t == 0) {
        float ts = 0.f;
        #pragma unroll
        for (int i = 0; i < 8; i++) ts += sm[i];
        inv_s = 1.0f / ts;
    }
    __syncthreads();
    float inv = inv_s;
    v0.x *= inv; v0.y *= inv; v0.z *= inv; v0.w *= inv;
    v1.x *= inv; v1.y *= inv; v1.z *= inv; v1.w *= inv;
    ((float4*)r)[t] = v0;
    ((float4*)r)[t + 256] = v1;
}

// ---------------- launch ----------------
extern "C" void kernel_launch(void* const* d_in, const int* in_sizes, int n_in,
                              void* d_out, int out_size)
{
    const float* X      = (const float*)d_in[0];
    const float* WQ     = (const float*)d_in[1];
    const float* WK     = (const float*)d_in[2];
    const float* WV     = (const float*)d_in[3];
    const float* WO     = (const float*)d_in[4];
    const float* attn_g = (const float*)d_in[5];
    const float* attn_b = (const float*)d_in[6];
    const float* ff_g   = (const float*)d_in[7];
    const float* ff_b   = (const float*)d_in[8];
    const float* fW1    = (const float*)d_in[9];
    const float* fb1    = (const float*)d_in[10];
    const float* fW2    = (const float*)d_in[11];
    const float* fb2    = (const float*)d_in[12];

    float* out  = (float*)d_out;
    float* attn = out + (size_t)NTOK * DMODEL;   // [B,H,T,T]

    float *nX, *Q, *K, *V, *Vt, *nv, *ss, *preff, *hidden;
    float *Wq, *Wk, *Wv, *Wot, *W1t, *W2t;
    cudaGetSymbolAddress((void**)&nX,     g_nX);
    cudaGetSymbolAddress((void**)&Q,      g_Q);
    cudaGetSymbolAddress((void**)&K,      g_Kb);
    cudaGetSymbolAddress((void**)&V,      g_V);
    cudaGetSymbolAddress((void**)&Vt,     g_Vt);
    cudaGetSymbolAddress((void**)&nv,     g_nv);
    cudaGetSymbolAddress((void**)&ss,     g_ss);
    cudaGetSymbolAddress((void**)&preff,  g_preff);
    cudaGetSymbolAddress((void**)&hidden, g_hidden);
    cudaGetSymbolAddress((void**)&Wq,     g_Wq);
    cudaGetSymbolAddress((void**)&Wk,     g_Wk);
    cudaGetSymbolAddress((void**)&Wv,     g_Wv);
    cudaGetSymbolAddress((void**)&Wot,    g_Wot);
    cudaGetSymbolAddress((void**)&W1t,    g_W1t);
    cudaGetSymbolAddress((void**)&W2t,    g_W2t);

    const int LIN_SMEM = (int)(Core<128, 2, 4>::STG * 2 * sizeof(uint32_t)); // 67584
    const int AV_SMEM  = (int)(Core<64, 4, 2>::STG * 2 * sizeof(uint32_t));  // 51200
    cudaFuncSetAttribute(linear_bf<false, false, false>, cudaFuncAttributeMaxDynamicSharedMemorySize, LIN_SMEM);
    cudaFuncSetAttribute(linear_bf<true, true, false>,   cudaFuncAttributeMaxDynamicSharedMemorySize, LIN_SMEM);
    cudaFuncSetAttribute(linear_bf<true, false, true>,   cudaFuncAttributeMaxDynamicSharedMemorySize, LIN_SMEM);
    cudaFuncSetAttribute(score_bf, cudaFuncAttributeMaxDynamicSharedMemorySize, LIN_SMEM);
    cudaFuncSetAttribute(av_bf,    cudaFuncAttributeMaxDynamicSharedMemorySize, AV_SMEM);

    dim3 tb(32, 8);

    // 1. nX = LN(X)
    ln_kernel<<<NTOK, 256>>>(X, attn_g, attn_b, nullptr, nX);

    // 2. weight transposes -> K-major [N, K] layouts
    transpose_tiled<<<dim3(2, 32, 16), tb>>>(WQ, Wq, DMODEL, HP, 65536LL, 65536LL);
    transpose_tiled<<<dim3(2, 32, 16), tb>>>(WK, Wk, DMODEL, HP, 65536LL, 65536LL);
    transpose_tiled<<<dim3(2, 32, 16), tb>>>(WV, Wv, DMODEL, HP, 65536LL, 65536LL);
    transpose_tiled<<<dim3(32, 32, 1), tb>>>(WO, Wot, DMODEL, DMODEL, 0LL, 0LL);
    transpose_tiled<<<dim3(FFDIM / 32, 32, 1), tb>>>(fW1, W1t, DMODEL, FFDIM, 0LL, 0LL);
    transpose_tiled<<<dim3(32, FFDIM / 32, 1), tb>>>(fW2, W2t, FFDIM, DMODEL, 0LL, 0LL);

    // 3. Q/K/V projections (bf16x2 mma)
    dim3 gQKV(DMODEL / 128, NTOK / 128);
    linear_bf<false, false, false><<<gQKV, 256, LIN_SMEM>>>(nX, Wq, nullptr, nullptr, Q, DMODEL, DMODEL);
    linear_bf<false, false, false><<<gQKV, 256, LIN_SMEM>>>(nX, Wk, nullptr, nullptr, K, DMODEL, DMODEL);
    linear_bf<false, false, false><<<gQKV, 256, LIN_SMEM>>>(nX, Wv, nullptr, nullptr, V, DMODEL, DMODEL);

    // 4. V transpose for AV
    vt_kernel<<<dim3(TLEN / 32, HP / 32, BATCH * NH), tb>>>(V, Vt);

    // 5. scores -> attn; 6. softmax in-place; 7. nv = attn @ V
    score_bf<<<dim3(TLEN / 128, TLEN / 128, BATCH * NH), 256, LIN_SMEM>>>(K, Q, attn);
    softmax_kernel<<<BATCH * NH * TLEN, 256>>>(attn);
    av_bf<<<dim3(TLEN / 128, 1, BATCH * NH), 256, AV_SMEM>>>(attn, Vt, nv);

    // 8. seq_summary = nv @ WO
    linear_bf<false, false, false><<<gQKV, 256, LIN_SMEM>>>(nv, Wot, nullptr, nullptr, ss, DMODEL, DMODEL);

    // 9. pre_ff = X + LN(ss)
    ln_kernel<<<NTOK, 256>>>(ss, ff_g, ff_b, X, preff);

    // 10. hidden = gelu(pre_ff @ fW1 + fb1)
    linear_bf<true, true, false><<<dim3(FFDIM / 128, NTOK / 128), 256, LIN_SMEM>>>(
        preff, W1t, fb1, nullptr, hidden, FFDIM, DMODEL);

    // 11. out = hidden @ fW2 + fb2 + pre_ff
    linear_bf<true, false, true><<<dim3(DMODEL / 128, NTOK / 128), 256, LIN_SMEM>>>(
        hidden, W2t, fb2, preff, out, DMODEL, FFDIM);
}